// round 14
// baseline (speedup 1.0000x reference)
#include <cuda_runtime.h>
#include <cuda_bf16.h>
#include <cstdint>

#define HID    1024
#define SEQ    2048
#define BATCH  2
#define HEADS  16
#define HDIM   64
#define ROWS   (BATCH * SEQ)   // 4096

// ---------------- scratch (device globals; no allocations allowed) ----------
__device__ __nv_bfloat16 g_xn  [ROWS * HID];
__device__ __nv_bfloat16 g_q   [ROWS * HID];
__device__ __nv_bfloat16 g_k   [ROWS * HID];
__device__ __nv_bfloat16 g_v   [ROWS * HID];
__device__ __nv_bfloat16 g_ctx [ROWS * HID];
__device__ __nv_bfloat16 g_wqkv[3 * HID * HID];
__device__ __nv_bfloat16 g_wo  [HID * HID];

// ---------------- helpers ----------------------------------------------------
__device__ __forceinline__ uint32_t smem_u32(const void* p) {
    return (uint32_t)__cvta_generic_to_shared(p);
}
__device__ __forceinline__ void cp16(uint32_t dst, const void* src) {
    asm volatile("cp.async.cg.shared.global [%0], [%1], 16;" :: "r"(dst), "l"(src));
}
#define CP_COMMIT() asm volatile("cp.async.commit_group;")
#define CP_WAIT0()  asm volatile("cp.async.wait_group 0;")
#define CP_WAIT1()  asm volatile("cp.async.wait_group 1;")

__device__ __forceinline__ void mma_bf16(float* c, const uint32_t* a, const uint32_t* b) {
    asm volatile(
        "mma.sync.aligned.m16n8k16.row.col.f32.bf16.bf16.f32 "
        "{%0,%1,%2,%3}, {%4,%5,%6,%7}, {%8,%9}, {%0,%1,%2,%3};"
        : "+f"(c[0]), "+f"(c[1]), "+f"(c[2]), "+f"(c[3])
        : "r"(a[0]), "r"(a[1]), "r"(a[2]), "r"(a[3]), "r"(b[0]), "r"(b[1]));
}
__device__ __forceinline__ void ldsm_x4(uint32_t* r, uint32_t addr) {
    asm volatile("ldmatrix.sync.aligned.m8n8.x4.shared.b16 {%0,%1,%2,%3}, [%4];"
        : "=r"(r[0]), "=r"(r[1]), "=r"(r[2]), "=r"(r[3]) : "r"(addr));
}
__device__ __forceinline__ void ldsm_x4_t(uint32_t* r, uint32_t addr) {
    asm volatile("ldmatrix.sync.aligned.m8n8.x4.trans.shared.b16 {%0,%1,%2,%3}, [%4];"
        : "=r"(r[0]), "=r"(r[1]), "=r"(r[2]), "=r"(r[3]) : "r"(addr));
}
__device__ __forceinline__ uint32_t ld32s(const __nv_bfloat16* p) {
    return *(const uint32_t*)p;
}
__device__ __forceinline__ uint32_t packbf(float lo, float hi) {
    __nv_bfloat162 t = __floats2bfloat162_rn(lo, hi);
    return *(uint32_t*)&t;
}
__device__ __forceinline__ float ex2(float x) {
    float y;
    asm("ex2.approx.ftz.f32 %0, %1;" : "=f"(y) : "f"(x));
    return y;
}
// ---- mbarrier helpers --------------------------------------------------------
__device__ __forceinline__ void mb_init(uint32_t mbar, uint32_t cnt) {
    asm volatile("mbarrier.init.shared.b64 [%0], %1;" :: "r"(mbar), "r"(cnt) : "memory");
}
__device__ __forceinline__ void mb_arrive(uint32_t mbar) {
    asm volatile("mbarrier.arrive.shared.b64 _, [%0];" :: "r"(mbar) : "memory");
}
__device__ __forceinline__ void cp_async_mb_arrive(uint32_t mbar) {
    asm volatile("cp.async.mbarrier.arrive.noinc.shared.b64 [%0];" :: "r"(mbar) : "memory");
}
__device__ __forceinline__ void mb_wait(uint32_t mbar, uint32_t parity) {
    asm volatile(
        "{\n\t.reg .pred P;\n\t"
        "W_%=:\n\t"
        "mbarrier.try_wait.parity.acquire.cta.shared::cta.b64 P, [%0], %1, 0x989680;\n\t"
        "@P bra D_%=;\n\t"
        "bra W_%=;\n\t"
        "D_%=:\n\t}"
        :: "r"(mbar), "r"(parity) : "memory");
}

// ---------------- fused weight-convert + LayerNorm ----------------------------
__global__ __launch_bounds__(256) void prep_kernel(
    const float* __restrict__ x, const float* __restrict__ lg,
    const float* __restrict__ lb, __nv_bfloat16* __restrict__ xn,
    const float4* __restrict__ s0, const float4* __restrict__ s1,
    const float4* __restrict__ s2, const float4* __restrict__ s3,
    __nv_bfloat162* __restrict__ dqkv, __nv_bfloat162* __restrict__ dwo)
{
    const int tid = threadIdx.x;
    if (blockIdx.y == 1) {
        const int i = blockIdx.x * 256 + tid;
        const int mat = i >> 18;
        const int j = i & 262143;
        const float4* src = (mat == 0) ? s0 : (mat == 1) ? s1 : (mat == 2) ? s2 : s3;
        __nv_bfloat162* d = (mat == 3) ? dwo : dqkv + (size_t)mat * (HID * HID / 2);
        const float4 v = src[j];
        d[2 * j + 0] = __floats2bfloat162_rn(v.x, v.y);
        d[2 * j + 1] = __floats2bfloat162_rn(v.z, v.w);
        return;
    }
    __shared__ float red[16];
    const int row = blockIdx.x;
    const float4 v = *(const float4*)(x + (size_t)row * HID + tid * 4);

    float s1v = v.x + v.y + v.z + v.w;
    float s2v = v.x * v.x + v.y * v.y + v.z * v.z + v.w * v.w;
    #pragma unroll
    for (int off = 16; off; off >>= 1) {
        s1v += __shfl_xor_sync(0xffffffffu, s1v, off);
        s2v += __shfl_xor_sync(0xffffffffu, s2v, off);
    }
    const int warp = tid >> 5, lane = tid & 31;
    if (lane == 0) { red[warp] = s1v; red[warp + 8] = s2v; }
    __syncthreads();
    if (tid < 32) {
        float a  = (lane < 8) ? red[lane]     : 0.f;
        float b2 = (lane < 8) ? red[lane + 8] : 0.f;
        #pragma unroll
        for (int off = 4; off; off >>= 1) {
            a  += __shfl_xor_sync(0xffffffffu, a,  off);
            b2 += __shfl_xor_sync(0xffffffffu, b2, off);
        }
        if (lane == 0) { red[0] = a; red[1] = b2; }
    }
    __syncthreads();
    const float mu  = red[0] * (1.f / HID);
    const float var = red[1] * (1.f / HID) - mu * mu;
    const float rs  = rsqrtf(var + 1e-5f);

    const float4 gv = *(const float4*)(lg + tid * 4);
    const float4 bv = *(const float4*)(lb + tid * 4);
    __nv_bfloat162* o = (__nv_bfloat162*)(xn + (size_t)row * HID + tid * 4);
    o[0] = __floats2bfloat162_rn((v.x - mu) * rs * gv.x + bv.x,
                                 (v.y - mu) * rs * gv.y + bv.y);
    o[1] = __floats2bfloat162_rn((v.z - mu) * rs * gv.z + bv.z,
                                 (v.w - mu) * rs * gv.w + bv.w);
}

// ---------------- bf16 mma GEMM, 128x128 tile (out-proj) ----------------------
#define LDK   72
#define TMAT  (128 * LDK)
#define TSTG  (2 * TMAT)
#define GEMM_SMEM (3 * TSTG * 2)

__global__ __launch_bounds__(256, 2) void mma_gemm(
    const __nv_bfloat16* __restrict__ A, const __nv_bfloat16* __restrict__ W,
    const float* __restrict__ bias, const float* __restrict__ resid,
    float* __restrict__ Cf)
{
    extern __shared__ __nv_bfloat16 gsm[];
    const int tid  = threadIdx.x;
    const int lane = tid & 31;
    const int wid  = tid >> 5;
    const int wm   = (wid >> 2) * 64;
    const int wn   = (wid & 3) * 32;
    const int row0 = blockIdx.y * 128, col0 = blockIdx.x * 128;
    const int g    = lane >> 2;
    const int t4   = lane & 3;

    const uint32_t s0 = smem_u32(gsm);

    auto load_chunk = [&](int kc, int stg) {
        const uint32_t sA = s0 + stg * TSTG * 2;
        const uint32_t sB = sA + TMAT * 2;
        const int kcol = kc * 64;
        #pragma unroll
        for (int it = 0; it < 4; it++) {
            const int id = it * 256 + tid;
            const int r = id >> 3;
            const int c = id & 7;
            const uint32_t off = (uint32_t)(r * LDK + c * 8) * 2;
            cp16(sA + off, A + (size_t)(row0 + r) * HID + kcol + c * 8);
            cp16(sB + off, W + (size_t)(col0 + r) * HID + kcol + c * 8);
        }
        CP_COMMIT();
    };

    float acc[4][4][4];
    #pragma unroll
    for (int i = 0; i < 4; i++)
        #pragma unroll
        for (int j = 0; j < 4; j++)
            #pragma unroll
            for (int r = 0; r < 4; r++) acc[i][j][r] = 0.f;

    load_chunk(0, 0);
    load_chunk(1, 1);

    const int arow = (lane & 7) + ((lane >> 3) & 1) * 8;
    const int akof = (lane >> 4) * 8;
    const int brow = (lane & 7) + ((lane >> 4) & 1) * 8;
    const int bkof = ((lane >> 3) & 1) * 8;

    for (int kc = 0; kc < 16; kc++) {
        if (kc < 15) { CP_WAIT1(); } else { CP_WAIT0(); }
        __syncthreads();
        if (kc + 2 < 16) load_chunk(kc + 2, (kc + 2) % 3);

        const uint32_t sAc = s0 + (kc % 3) * TSTG * 2;
        const uint32_t sBc = sAc + TMAT * 2;
        #pragma unroll
        for (int kk = 0; kk < 64; kk += 16) {
            uint32_t af[4][4], bf[2][4];
            #pragma unroll
            for (int mf = 0; mf < 4; mf++)
                ldsm_x4(af[mf], sAc + ((wm + mf * 16 + arow) * LDK + kk + akof) * 2);
            #pragma unroll
            for (int nfp = 0; nfp < 2; nfp++)
                ldsm_x4(bf[nfp], sBc + ((wn + nfp * 16 + brow) * LDK + kk + bkof) * 2);
            #pragma unroll
            for (int mf = 0; mf < 4; mf++)
                #pragma unroll
                for (int nfp = 0; nfp < 2; nfp++) {
                    mma_bf16(acc[mf][2 * nfp],     af[mf], bf[nfp]);
                    mma_bf16(acc[mf][2 * nfp + 1], af[mf], bf[nfp] + 2);
                }
        }
    }

    const int t2 = t4 * 2;
    #pragma unroll
    for (int mf = 0; mf < 4; mf++) {
        #pragma unroll
        for (int nf = 0; nf < 4; nf++) {
            const int r = row0 + wm + mf * 16 + g;
            const int c = col0 + wn + nf * 8 + t2;
            const float2 bb = *(const float2*)&bias[c];
            const float2 r0v = *(const float2*)&resid[(size_t)r * HID + c];
            const float2 r1v = *(const float2*)&resid[(size_t)(r + 8) * HID + c];
            float2 a0 = { acc[mf][nf][0] + bb.x + r0v.x, acc[mf][nf][1] + bb.y + r0v.y };
            float2 a1 = { acc[mf][nf][2] + bb.x + r1v.x, acc[mf][nf][3] + bb.y + r1v.y };
            *(float2*)&Cf[(size_t)r * HID + c] = a0;
            *(float2*)&Cf[(size_t)(r + 8) * HID + c] = a1;
        }
    }
}

// ---------------- bf16 mma GEMM, 256x128 tile (fused QKV) ---------------------
// 512 threads, 16 warps (4x4), warp tile 64x32 (same inner code), BK=64,
// 3-stage cp.async. Halves weight L2 traffic vs 128x128 tiles.
#define BTM   (256 * LDK)              // A halves per stage
#define BTN   (128 * LDK)              // B halves per stage
#define BSTG  (BTM + BTN)
#define GEMM2_SMEM (3 * BSTG * 2)      // 165888 B

__global__ __launch_bounds__(512, 1) void mma_gemm_big(
    const __nv_bfloat16* __restrict__ A, const __nv_bfloat16* __restrict__ W,
    const float* __restrict__ b0p, const float* __restrict__ b1p,
    const float* __restrict__ b2p,
    __nv_bfloat16* __restrict__ C0, __nv_bfloat16* __restrict__ C1,
    __nv_bfloat16* __restrict__ C2)
{
    extern __shared__ __nv_bfloat16 gsm[];
    const int tid  = threadIdx.x;
    const int lane = tid & 31;
    const int wid  = tid >> 5;
    const int wm   = (wid >> 2) * 64;    // 0..192
    const int wn   = (wid & 3) * 32;     // 0..96
    const int row0 = blockIdx.y * 256, col0 = blockIdx.x * 128;
    const int g    = lane >> 2;
    const int t4   = lane & 3;

    const uint32_t s0 = smem_u32(gsm);

    auto load_chunk = [&](int kc, int stg) {
        const uint32_t sA = s0 + stg * BSTG * 2;
        const uint32_t sB = sA + BTM * 2;
        const int kcol = kc * 64;
        // A: 256 rows x 8 chunks = 2048 ; 4 per thread
        #pragma unroll
        for (int it = 0; it < 4; it++) {
            const int id = it * 512 + tid;
            const int r = id >> 3;
            const int c = id & 7;
            cp16(sA + (uint32_t)(r * LDK + c * 8) * 2,
                 A + (size_t)(row0 + r) * HID + kcol + c * 8);
        }
        // B: 128 rows x 8 chunks = 1024 ; 2 per thread
        #pragma unroll
        for (int it = 0; it < 2; it++) {
            const int id = it * 512 + tid;
            const int r = id >> 3;
            const int c = id & 7;
            cp16(sB + (uint32_t)(r * LDK + c * 8) * 2,
                 W + (size_t)(col0 + r) * HID + kcol + c * 8);
        }
        CP_COMMIT();
    };

    float acc[4][4][4];
    #pragma unroll
    for (int i = 0; i < 4; i++)
        #pragma unroll
        for (int j = 0; j < 4; j++)
            #pragma unroll
            for (int r = 0; r < 4; r++) acc[i][j][r] = 0.f;

    load_chunk(0, 0);
    load_chunk(1, 1);

    const int arow = (lane & 7) + ((lane >> 3) & 1) * 8;
    const int akof = (lane >> 4) * 8;
    const int brow = (lane & 7) + ((lane >> 4) & 1) * 8;
    const int bkof = ((lane >> 3) & 1) * 8;

    for (int kc = 0; kc < 16; kc++) {
        if (kc < 15) { CP_WAIT1(); } else { CP_WAIT0(); }
        __syncthreads();
        if (kc + 2 < 16) load_chunk(kc + 2, (kc + 2) % 3);

        const uint32_t sAc = s0 + (kc % 3) * BSTG * 2;
        const uint32_t sBc = sAc + BTM * 2;
        #pragma unroll
        for (int kk = 0; kk < 64; kk += 16) {
            uint32_t af[4][4], bf[2][4];
            #pragma unroll
            for (int mf = 0; mf < 4; mf++)
                ldsm_x4(af[mf], sAc + ((wm + mf * 16 + arow) * LDK + kk + akof) * 2);
            #pragma unroll
            for (int nfp = 0; nfp < 2; nfp++)
                ldsm_x4(bf[nfp], sBc + ((wn + nfp * 16 + brow) * LDK + kk + bkof) * 2);
            #pragma unroll
            for (int mf = 0; mf < 4; mf++)
                #pragma unroll
                for (int nfp = 0; nfp < 2; nfp++) {
                    mma_bf16(acc[mf][2 * nfp],     af[mf], bf[nfp]);
                    mma_bf16(acc[mf][2 * nfp + 1], af[mf], bf[nfp] + 2);
                }
        }
    }

    const int sel  = col0 >> 10;
    const int colL = col0 & 1023;
    const float* bias = (sel == 0) ? b0p : (sel == 1) ? b1p : b2p;
    __nv_bfloat16* Cb = (sel == 0) ? C0 : (sel == 1) ? C1 : C2;
    const int t2 = t4 * 2;
    #pragma unroll
    for (int mf = 0; mf < 4; mf++) {
        #pragma unroll
        for (int nf = 0; nf < 4; nf++) {
            const int r = row0 + wm + mf * 16 + g;
            const int c = colL + wn + nf * 8 + t2;
            const float2 bb = *(const float2*)&bias[c];
            *(uint32_t*)&Cb[(size_t)r * HID + c] =
                packbf(acc[mf][nf][0] + bb.x, acc[mf][nf][1] + bb.y);
            *(uint32_t*)&Cb[(size_t)(r + 8) * HID + c] =
                packbf(acc[mf][nf][2] + bb.x, acc[mf][nf][3] + bb.y);
        }
    }
}

// ---------------- Flash attention: mbarrier free-running pipeline -------------
#define LDATT 72
#define NSTG  4
#define KVST  (64 * LDATT)
#define SMEM_ATTN ((128 * LDATT + 2 * NSTG * KVST) * 2)   // 92160 B
#define SM_SCALE 0.18033688011112042f                     // 0.125 * log2(e)

__global__ __launch_bounds__(256, 2) void attn_mma(
    const __nv_bfloat16* __restrict__ Q, const __nv_bfloat16* __restrict__ K,
    const __nv_bfloat16* __restrict__ V, __nv_bfloat16* __restrict__ O)
{
    extern __shared__ __nv_bfloat16 sm[];
    __nv_bfloat16* QP = sm;
    __nv_bfloat16* Ks = sm + 128 * LDATT;
    __nv_bfloat16* Vs = Ks + NSTG * KVST;
    __shared__ uint64_t mbars[2 * NSTG];

    const int tid  = threadIdx.x;
    const int lane = tid & 31;
    const int wid  = tid >> 5;
    const int g    = lane >> 2;
    const int t4   = lane & 3;
    const int q0   = blockIdx.x << 7;
    const size_t base = (size_t)blockIdx.z * SEQ * HID + (size_t)blockIdx.y * HDIM;
    const __nv_bfloat16* Qb = Q + base;
    const __nv_bfloat16* Kb = K + base;
    const __nv_bfloat16* Vb = V + base;
    const int rw = wid * 16 + g;

    const uint32_t sQP = smem_u32(QP);
    const uint32_t sK  = smem_u32(Ks);
    const uint32_t sV  = smem_u32(Vs);
    const uint32_t mb  = smem_u32(mbars);

    if (tid == 0) {
        #pragma unroll
        for (int s = 0; s < NSTG; s++) {
            mb_init(mb + s * 8, 256);
            mb_init(mb + 32 + s * 8, 8);
        }
    }
    __syncthreads();

    auto load_kv = [&](int kt, int stg) {
        const int k0n = kt << 6;
        const uint32_t so = (uint32_t)stg * KVST * 2;
        const int r = tid >> 2, c = (tid & 3) * 16;
        const __nv_bfloat16* ksrc = Kb + (size_t)(k0n + r) * HID + c;
        const __nv_bfloat16* vsrc = Vb + (size_t)(k0n + r) * HID + c;
        const uint32_t kd = sK + so + (r * LDATT + c) * 2;
        const uint32_t vd = sV + so + (r * LDATT + c) * 2;
        cp16(kd, ksrc); cp16(kd + 16, ksrc + 8);
        cp16(vd, vsrc); cp16(vd + 16, vsrc + 8);
        cp_async_mb_arrive(mb + stg * 8);
    };

    {
        const int r = tid >> 1, c = (tid & 1) * 32;
        const __nv_bfloat16* src = Qb + (size_t)(q0 + r) * HID + c;
        const uint32_t dst = sQP + (r * LDATT + c) * 2;
        cp16(dst, src); cp16(dst + 16, src + 8);
        cp16(dst + 32, src + 16); cp16(dst + 48, src + 24);
    }
    load_kv(0, 0);
    load_kv(1, 1);
    load_kv(2, 2);

    mb_wait(mb + 0, 0);

    uint32_t qf[4][4];
    #pragma unroll
    for (int k4 = 0; k4 < 4; k4++) {
        const int kb = k4 * 16 + 2 * t4;
        qf[k4][0] = ld32s(&QP[rw * LDATT + kb]);
        qf[k4][1] = ld32s(&QP[(rw + 8) * LDATT + kb]);
        qf[k4][2] = ld32s(&QP[rw * LDATT + kb + 8]);
        qf[k4][3] = ld32s(&QP[(rw + 8) * LDATT + kb + 8]);
    }

    float m0 = -1e30f, m1 = -1e30f, l0 = 0.f, l1 = 0.f;
    float oacc[8][4];
    #pragma unroll
    for (int nf = 0; nf < 8; nf++)
        #pragma unroll
        for (int j = 0; j < 4; j++) oacc[nf][j] = 0.f;

    const int brow = (lane & 7) + ((lane >> 4) & 1) * 8;
    const int bkof = ((lane >> 3) & 1) * 8;

    int cph = 0, pph = 0;

    for (int kt = 0; kt < 32; kt++) {
        {
            const int tp = kt + 3;
            if (tp < 32) {
                const int ps = tp & 3;
                if (tp > 3) mb_wait(mb + 32 + ps * 8, pph);
                load_kv(tp, ps);
                if (tp > 3 && ps == 3) pph ^= 1;
            }
        }

        const int cs = kt & 3;
        mb_wait(mb + cs * 8, cph);

        const uint32_t sKc = sK + (uint32_t)cs * KVST * 2;
        const uint32_t sVc = sV + (uint32_t)cs * KVST * 2;

        float sacc[8][4];
        #pragma unroll
        for (int nf = 0; nf < 8; nf++)
            #pragma unroll
            for (int j = 0; j < 4; j++) sacc[nf][j] = 0.f;

        #pragma unroll
        for (int k4 = 0; k4 < 4; k4++) {
            const int kb0 = k4 * 16;
            #pragma unroll
            for (int nfp = 0; nfp < 4; nfp++) {
                uint32_t bfr[4];
                ldsm_x4(bfr, sKc + ((nfp * 16 + brow) * LDATT + kb0 + bkof) * 2);
                mma_bf16(sacc[2 * nfp],     qf[k4], bfr);
                mma_bf16(sacc[2 * nfp + 1], qf[k4], bfr + 2);
            }
        }

        #pragma unroll
        for (int ch = 0; ch < 2; ch++) {
            const int nfb = ch * 4;
            float mx0 = -1e30f, mx1 = -1e30f;
            #pragma unroll
            for (int nf = nfb; nf < nfb + 4; nf++) {
                mx0 = fmaxf(mx0, fmaxf(sacc[nf][0], sacc[nf][1]));
                mx1 = fmaxf(mx1, fmaxf(sacc[nf][2], sacc[nf][3]));
            }
            mx0 = fmaxf(mx0, __shfl_xor_sync(0xffffffffu, mx0, 1));
            mx0 = fmaxf(mx0, __shfl_xor_sync(0xffffffffu, mx0, 2));
            mx1 = fmaxf(mx1, __shfl_xor_sync(0xffffffffu, mx1, 1));
            mx1 = fmaxf(mx1, __shfl_xor_sync(0xffffffffu, mx1, 2));

            const float mn0 = fmaxf(m0, mx0 * SM_SCALE);
            const float mn1 = fmaxf(m1, mx1 * SM_SCALE);
            const float corr0 = ex2(m0 - mn0), corr1 = ex2(m1 - mn1);
            m0 = mn0; m1 = mn1;

            float rs0 = 0.f, rs1 = 0.f;
            #pragma unroll
            for (int nf = nfb; nf < nfb + 4; nf++) {
                sacc[nf][0] = ex2(fmaf(sacc[nf][0], SM_SCALE, -mn0));
                sacc[nf][1] = ex2(fmaf(sacc[nf][1], SM_SCALE, -mn0));
                sacc[nf][2] = ex2(fmaf(sacc[nf][2], SM_SCALE, -mn1));
                sacc[nf][3] = ex2(fmaf(sacc[nf][3], SM_SCALE, -mn1));
                rs0 += sacc[nf][0] + sacc[nf][1];
                rs1 += sacc[nf][2] + sacc[nf][3];
            }
            rs0 += __shfl_xor_sync(0xffffffffu, rs0, 1);
            rs0 += __shfl_xor_sync(0xffffffffu, rs0, 2);
            rs1 += __shfl_xor_sync(0xffffffffu, rs1, 1);
            rs1 += __shfl_xor_sync(0xffffffffu, rs1, 2);
            l0 = l0 * corr0 + rs0;
            l1 = l1 * corr1 + rs1;
            #pragma unroll
            for (int nf = 0; nf < 8; nf++) {
                oacc[nf][0] *= corr0; oacc[nf][1] *= corr0;
                oacc[nf][2] *= corr1; oacc[nf][3] *= corr1;
            }

            #pragma unroll
            for (int kh = 0; kh < 2; kh++) {
                const int k4 = 2 * ch + kh;
                uint32_t a[4];
                a[0] = packbf(sacc[2 * k4][0],     sacc[2 * k4][1]);
                a[1] = packbf(sacc[2 * k4][2],     sacc[2 * k4][3]);
                a[2] = packbf(sacc[2 * k4 + 1][0], sacc[2 * k4 + 1][1]);
                a[3] = packbf(sacc[2 * k4 + 1][2], sacc[2 * k4 + 1][3]);
                const int kk = k4 * 16;
                #pragma unroll
                for (int np = 0; np < 4; np++) {
                    uint32_t r[4];
                    const uint32_t addr = sVc +
                        ((kk + (lane & 15)) * LDATT + np * 16 + ((lane >> 4) << 3)) * 2;
                    ldsm_x4_t(r, addr);
                    mma_bf16(oacc[2 * np],     a, r);
                    mma_bf16(oacc[2 * np + 1], a, r + 2);
                }
            }
        }

        if (lane == 0) mb_arrive(mb + 32 + cs * 8);
        if (cs == 3) cph ^= 1;
    }

    const float inv0 = 1.f / l0, inv1 = 1.f / l1;
    #pragma unroll
    for (int nf = 0; nf < 8; nf++) {
        const int c = nf * 8 + 2 * t4;
        *(uint32_t*)&O[base + (size_t)(q0 + rw) * HID + c] =
            packbf(oacc[nf][0] * inv0, oacc[nf][1] * inv0);
        *(uint32_t*)&O[base + (size_t)(q0 + rw + 8) * HID + c] =
            packbf(oacc[nf][2] * inv1, oacc[nf][3] * inv1);
    }
}

// ---------------- launch -------------------------------------------------------
extern "C" void kernel_launch(void* const* d_in, const int* in_sizes, int n_in,
                              void* d_out, int out_size)
{
    const float* x    = (const float*)d_in[0];
    const float* Wq   = (const float*)d_in[1];
    const float* bq   = (const float*)d_in[2];
    const float* Wk   = (const float*)d_in[3];
    const float* bk   = (const float*)d_in[4];
    const float* Wv   = (const float*)d_in[5];
    const float* bv   = (const float*)d_in[6];
    const float* Wo   = (const float*)d_in[7];
    const float* bo   = (const float*)d_in[8];
    const float* ln_g = (const float*)d_in[9];
    const float* ln_b = (const float*)d_in[10];
    float* out = (float*)d_out;

    __nv_bfloat16 *xn_p, *q_p, *k_p, *v_p, *ctx_p, *wqkv_p, *wo_p;
    cudaGetSymbolAddress((void**)&xn_p,   g_xn);
    cudaGetSymbolAddress((void**)&q_p,    g_q);
    cudaGetSymbolAddress((void**)&k_p,    g_k);
    cudaGetSymbolAddress((void**)&v_p,    g_v);
    cudaGetSymbolAddress((void**)&ctx_p,  g_ctx);
    cudaGetSymbolAddress((void**)&wqkv_p, g_wqkv);
    cudaGetSymbolAddress((void**)&wo_p,   g_wo);

    cudaFuncSetAttribute(attn_mma,
        cudaFuncAttributeMaxDynamicSharedMemorySize, SMEM_ATTN);
    cudaFuncSetAttribute(mma_gemm,
        cudaFuncAttributeMaxDynamicSharedMemorySize, GEMM_SMEM);
    cudaFuncSetAttribute(mma_gemm_big,
        cudaFuncAttributeMaxDynamicSharedMemorySize, GEMM2_SMEM);

    // 0) fused LayerNorm + weight conversion
    dim3 pg(4096, 2);
    prep_kernel<<<pg, 256>>>(x, ln_g, ln_b, xn_p,
                             (const float4*)Wq, (const float4*)Wk,
                             (const float4*)Wv, (const float4*)Wo,
                             (__nv_bfloat162*)wqkv_p, (__nv_bfloat162*)wo_p);

    // 1) fused QKV projection: 256x128 tiles, N=3072
    dim3 gq(3 * HID / 128, ROWS / 256);
    mma_gemm_big<<<gq, 512, GEMM2_SMEM>>>(xn_p, wqkv_p, bq, bk, bv,
                                          q_p, k_p, v_p);

    // 2) attention (free-running mbarrier pipeline)
    dim3 ag(SEQ / 128, HEADS, BATCH);
    attn_mma<<<ag, 256, SMEM_ATTN>>>(q_p, k_p, v_p, ctx_p);

    // 3) output projection + bias + residual (fp32 out), 128x128 tiles
    dim3 go(HID / 128, ROWS / 128);
    mma_gemm<<<go, 256, GEMM_SMEM>>>(ctx_p, wo_p, bo, x, out);
}

// round 15
// speedup vs baseline: 1.0379x; 1.0379x over previous
#include <cuda_runtime.h>
#include <cuda_bf16.h>
#include <cstdint>

#define HID    1024
#define SEQ    2048
#define BATCH  2
#define HEADS  16
#define HDIM   64
#define ROWS   (BATCH * SEQ)   // 4096

// ---------------- scratch (device globals; no allocations allowed) ----------
__device__ __nv_bfloat16 g_xn  [ROWS * HID];
__device__ __nv_bfloat16 g_q   [ROWS * HID];
__device__ __nv_bfloat16 g_k   [ROWS * HID];
__device__ __nv_bfloat16 g_v   [ROWS * HID];
__device__ __nv_bfloat16 g_ctx [ROWS * HID];
__device__ __nv_bfloat16 g_wqkv[3 * HID * HID];
__device__ __nv_bfloat16 g_wo  [HID * HID];

// ---------------- helpers ----------------------------------------------------
__device__ __forceinline__ uint32_t smem_u32(const void* p) {
    return (uint32_t)__cvta_generic_to_shared(p);
}
__device__ __forceinline__ void cp16(uint32_t dst, const void* src) {
    asm volatile("cp.async.cg.shared.global [%0], [%1], 16;" :: "r"(dst), "l"(src));
}
#define CP_COMMIT() asm volatile("cp.async.commit_group;")
#define CP_WAIT0()  asm volatile("cp.async.wait_group 0;")
#define CP_WAIT1()  asm volatile("cp.async.wait_group 1;")

__device__ __forceinline__ void mma_bf16(float* c, const uint32_t* a, const uint32_t* b) {
    asm volatile(
        "mma.sync.aligned.m16n8k16.row.col.f32.bf16.bf16.f32 "
        "{%0,%1,%2,%3}, {%4,%5,%6,%7}, {%8,%9}, {%0,%1,%2,%3};"
        : "+f"(c[0]), "+f"(c[1]), "+f"(c[2]), "+f"(c[3])
        : "r"(a[0]), "r"(a[1]), "r"(a[2]), "r"(a[3]), "r"(b[0]), "r"(b[1]));
}
__device__ __forceinline__ void ldsm_x4(uint32_t* r, uint32_t addr) {
    asm volatile("ldmatrix.sync.aligned.m8n8.x4.shared.b16 {%0,%1,%2,%3}, [%4];"
        : "=r"(r[0]), "=r"(r[1]), "=r"(r[2]), "=r"(r[3]) : "r"(addr));
}
__device__ __forceinline__ void ldsm_x4_t(uint32_t* r, uint32_t addr) {
    asm volatile("ldmatrix.sync.aligned.m8n8.x4.trans.shared.b16 {%0,%1,%2,%3}, [%4];"
        : "=r"(r[0]), "=r"(r[1]), "=r"(r[2]), "=r"(r[3]) : "r"(addr));
}
__device__ __forceinline__ uint32_t ld32s(const __nv_bfloat16* p) {
    return *(const uint32_t*)p;
}
__device__ __forceinline__ uint32_t packbf(float lo, float hi) {
    __nv_bfloat162 t = __floats2bfloat162_rn(lo, hi);
    return *(uint32_t*)&t;
}
__device__ __forceinline__ float ex2(float x) {
    float y;
    asm("ex2.approx.ftz.f32 %0, %1;" : "=f"(y) : "f"(x));
    return y;
}
// ---- mbarrier helpers --------------------------------------------------------
__device__ __forceinline__ void mb_init(uint32_t mbar, uint32_t cnt) {
    asm volatile("mbarrier.init.shared.b64 [%0], %1;" :: "r"(mbar), "r"(cnt) : "memory");
}
__device__ __forceinline__ void mb_arrive(uint32_t mbar) {
    asm volatile("mbarrier.arrive.shared.b64 _, [%0];" :: "r"(mbar) : "memory");
}
__device__ __forceinline__ void cp_async_mb_arrive(uint32_t mbar) {
    asm volatile("cp.async.mbarrier.arrive.noinc.shared.b64 [%0];" :: "r"(mbar) : "memory");
}
__device__ __forceinline__ void mb_wait(uint32_t mbar, uint32_t parity) {
    asm volatile(
        "{\n\t.reg .pred P;\n\t"
        "W_%=:\n\t"
        "mbarrier.try_wait.parity.acquire.cta.shared::cta.b64 P, [%0], %1, 0x989680;\n\t"
        "@P bra D_%=;\n\t"
        "bra W_%=;\n\t"
        "D_%=:\n\t}"
        :: "r"(mbar), "r"(parity) : "memory");
}

// ---------------- fused weight-convert + LayerNorm ----------------------------
__global__ __launch_bounds__(256) void prep_kernel(
    const float* __restrict__ x, const float* __restrict__ lg,
    const float* __restrict__ lb, __nv_bfloat16* __restrict__ xn,
    const float4* __restrict__ s0, const float4* __restrict__ s1,
    const float4* __restrict__ s2, const float4* __restrict__ s3,
    __nv_bfloat162* __restrict__ dqkv, __nv_bfloat162* __restrict__ dwo)
{
    const int tid = threadIdx.x;
    if (blockIdx.y == 1) {
        const int i = blockIdx.x * 256 + tid;
        const int mat = i >> 18;
        const int j = i & 262143;
        const float4* src = (mat == 0) ? s0 : (mat == 1) ? s1 : (mat == 2) ? s2 : s3;
        __nv_bfloat162* d = (mat == 3) ? dwo : dqkv + (size_t)mat * (HID * HID / 2);
        const float4 v = src[j];
        d[2 * j + 0] = __floats2bfloat162_rn(v.x, v.y);
        d[2 * j + 1] = __floats2bfloat162_rn(v.z, v.w);
        return;
    }
    __shared__ float red[16];
    const int row = blockIdx.x;
    const float4 v = *(const float4*)(x + (size_t)row * HID + tid * 4);

    float s1v = v.x + v.y + v.z + v.w;
    float s2v = v.x * v.x + v.y * v.y + v.z * v.z + v.w * v.w;
    #pragma unroll
    for (int off = 16; off; off >>= 1) {
        s1v += __shfl_xor_sync(0xffffffffu, s1v, off);
        s2v += __shfl_xor_sync(0xffffffffu, s2v, off);
    }
    const int warp = tid >> 5, lane = tid & 31;
    if (lane == 0) { red[warp] = s1v; red[warp + 8] = s2v; }
    __syncthreads();
    if (tid < 32) {
        float a  = (lane < 8) ? red[lane]     : 0.f;
        float b2 = (lane < 8) ? red[lane + 8] : 0.f;
        #pragma unroll
        for (int off = 4; off; off >>= 1) {
            a  += __shfl_xor_sync(0xffffffffu, a,  off);
            b2 += __shfl_xor_sync(0xffffffffu, b2, off);
        }
        if (lane == 0) { red[0] = a; red[1] = b2; }
    }
    __syncthreads();
    const float mu  = red[0] * (1.f / HID);
    const float var = red[1] * (1.f / HID) - mu * mu;
    const float rs  = rsqrtf(var + 1e-5f);

    const float4 gv = *(const float4*)(lg + tid * 4);
    const float4 bv = *(const float4*)(lb + tid * 4);
    __nv_bfloat162* o = (__nv_bfloat162*)(xn + (size_t)row * HID + tid * 4);
    o[0] = __floats2bfloat162_rn((v.x - mu) * rs * gv.x + bv.x,
                                 (v.y - mu) * rs * gv.y + bv.y);
    o[1] = __floats2bfloat162_rn((v.z - mu) * rs * gv.z + bv.z,
                                 (v.w - mu) * rs * gv.w + bv.w);
}

// ---------------- bf16 mma GEMM (fused QKV or out-proj) -----------------------
#define LDK   72
#define TMAT  (128 * LDK)
#define TSTG  (2 * TMAT)
#define GEMM_SMEM (3 * TSTG * 2)

__global__ __launch_bounds__(256, 2) void mma_gemm(
    const __nv_bfloat16* __restrict__ A, const __nv_bfloat16* __restrict__ W,
    const float* __restrict__ b0p, const float* __restrict__ b1p,
    const float* __restrict__ b2p, const float* __restrict__ resid,
    __nv_bfloat16* __restrict__ C0, __nv_bfloat16* __restrict__ C1,
    __nv_bfloat16* __restrict__ C2, float* __restrict__ Cf, int out_fp32)
{
    extern __shared__ __nv_bfloat16 gsm[];
    const int tid  = threadIdx.x;
    const int lane = tid & 31;
    const int wid  = tid >> 5;
    const int wm   = (wid >> 2) * 64;
    const int wn   = (wid & 3) * 32;
    const int row0 = blockIdx.y * 128, col0 = blockIdx.x * 128;
    const int g    = lane >> 2;
    const int t4   = lane & 3;

    const uint32_t s0 = smem_u32(gsm);

    auto load_chunk = [&](int kc, int stg) {
        const uint32_t sA = s0 + stg * TSTG * 2;
        const uint32_t sB = sA + TMAT * 2;
        const int kcol = kc * 64;
        #pragma unroll
        for (int it = 0; it < 4; it++) {
            const int id = it * 256 + tid;
            const int r = id >> 3;
            const int c = id & 7;
            const uint32_t off = (uint32_t)(r * LDK + c * 8) * 2;
            cp16(sA + off, A + (size_t)(row0 + r) * HID + kcol + c * 8);
            cp16(sB + off, W + (size_t)(col0 + r) * HID + kcol + c * 8);
        }
        CP_COMMIT();
    };

    float acc[4][4][4];
    #pragma unroll
    for (int i = 0; i < 4; i++)
        #pragma unroll
        for (int j = 0; j < 4; j++)
            #pragma unroll
            for (int r = 0; r < 4; r++) acc[i][j][r] = 0.f;

    load_chunk(0, 0);
    load_chunk(1, 1);

    const int arow = (lane & 7) + ((lane >> 3) & 1) * 8;
    const int akof = (lane >> 4) * 8;
    const int brow = (lane & 7) + ((lane >> 4) & 1) * 8;
    const int bkof = ((lane >> 3) & 1) * 8;

    for (int kc = 0; kc < 16; kc++) {
        if (kc < 15) { CP_WAIT1(); } else { CP_WAIT0(); }
        __syncthreads();
        if (kc + 2 < 16) load_chunk(kc + 2, (kc + 2) % 3);

        const uint32_t sAc = s0 + (kc % 3) * TSTG * 2;
        const uint32_t sBc = sAc + TMAT * 2;
        #pragma unroll
        for (int kk = 0; kk < 64; kk += 16) {
            uint32_t af[4][4], bf[2][4];
            #pragma unroll
            for (int mf = 0; mf < 4; mf++)
                ldsm_x4(af[mf], sAc + ((wm + mf * 16 + arow) * LDK + kk + akof) * 2);
            #pragma unroll
            for (int nfp = 0; nfp < 2; nfp++)
                ldsm_x4(bf[nfp], sBc + ((wn + nfp * 16 + brow) * LDK + kk + bkof) * 2);
            #pragma unroll
            for (int mf = 0; mf < 4; mf++)
                #pragma unroll
                for (int nfp = 0; nfp < 2; nfp++) {
                    mma_bf16(acc[mf][2 * nfp],     af[mf], bf[nfp]);
                    mma_bf16(acc[mf][2 * nfp + 1], af[mf], bf[nfp] + 2);
                }
        }
    }

    const int sel  = col0 >> 10;
    const int colL = col0 & 1023;
    const float* bias = (sel == 0) ? b0p : (sel == 1) ? b1p : b2p;
    __nv_bfloat16* Cb = (sel == 0) ? C0 : (sel == 1) ? C1 : C2;
    const int t2 = t4 * 2;
    #pragma unroll
    for (int mf = 0; mf < 4; mf++) {
        #pragma unroll
        for (int nf = 0; nf < 4; nf++) {
            const int r = row0 + wm + mf * 16 + g;
            const int c = colL + wn + nf * 8 + t2;
            const float2 bb = *(const float2*)&bias[c];
            float o00 = acc[mf][nf][0] + bb.x, o01 = acc[mf][nf][1] + bb.y;
            float o10 = acc[mf][nf][2] + bb.x, o11 = acc[mf][nf][3] + bb.y;
            if (out_fp32) {
                const float2 r0v = *(const float2*)&resid[(size_t)r * HID + c];
                const float2 r1v = *(const float2*)&resid[(size_t)(r + 8) * HID + c];
                float2 a0 = { o00 + r0v.x, o01 + r0v.y };
                float2 a1 = { o10 + r1v.x, o11 + r1v.y };
                *(float2*)&Cf[(size_t)r * HID + c] = a0;
                *(float2*)&Cf[(size_t)(r + 8) * HID + c] = a1;
            } else {
                *(uint32_t*)&Cb[(size_t)r * HID + c] = packbf(o00, o01);
                *(uint32_t*)&Cb[(size_t)(r + 8) * HID + c] = packbf(o10, o11);
            }
        }
    }
}

// ---------------- Flash attention: mbarrier pipeline + corr-skip --------------
#define LDATT 72
#define NSTG  4
#define KVST  (64 * LDATT)
#define SMEM_ATTN ((128 * LDATT + 2 * NSTG * KVST) * 2)   // 92160 B
#define SM_SCALE 0.18033688011112042f                     // 0.125 * log2(e)

__global__ __launch_bounds__(256, 2) void attn_mma(
    const __nv_bfloat16* __restrict__ Q, const __nv_bfloat16* __restrict__ K,
    const __nv_bfloat16* __restrict__ V, __nv_bfloat16* __restrict__ O)
{
    extern __shared__ __nv_bfloat16 sm[];
    __nv_bfloat16* QP = sm;
    __nv_bfloat16* Ks = sm + 128 * LDATT;
    __nv_bfloat16* Vs = Ks + NSTG * KVST;
    __shared__ uint64_t mbars[2 * NSTG];

    const int tid  = threadIdx.x;
    const int lane = tid & 31;
    const int wid  = tid >> 5;
    const int g    = lane >> 2;
    const int t4   = lane & 3;
    const int q0   = blockIdx.x << 7;
    const size_t base = (size_t)blockIdx.z * SEQ * HID + (size_t)blockIdx.y * HDIM;
    const __nv_bfloat16* Qb = Q + base;
    const __nv_bfloat16* Kb = K + base;
    const __nv_bfloat16* Vb = V + base;
    const int rw = wid * 16 + g;

    const uint32_t sQP = smem_u32(QP);
    const uint32_t sK  = smem_u32(Ks);
    const uint32_t sV  = smem_u32(Vs);
    const uint32_t mb  = smem_u32(mbars);

    if (tid == 0) {
        #pragma unroll
        for (int s = 0; s < NSTG; s++) {
            mb_init(mb + s * 8, 256);
            mb_init(mb + 32 + s * 8, 8);
        }
    }
    __syncthreads();

    auto load_kv = [&](int kt, int stg) {
        const int k0n = kt << 6;
        const uint32_t so = (uint32_t)stg * KVST * 2;
        const int r = tid >> 2, c = (tid & 3) * 16;
        const __nv_bfloat16* ksrc = Kb + (size_t)(k0n + r) * HID + c;
        const __nv_bfloat16* vsrc = Vb + (size_t)(k0n + r) * HID + c;
        const uint32_t kd = sK + so + (r * LDATT + c) * 2;
        const uint32_t vd = sV + so + (r * LDATT + c) * 2;
        cp16(kd, ksrc); cp16(kd + 16, ksrc + 8);
        cp16(vd, vsrc); cp16(vd + 16, vsrc + 8);
        cp_async_mb_arrive(mb + stg * 8);
    };

    {
        const int r = tid >> 1, c = (tid & 1) * 32;
        const __nv_bfloat16* src = Qb + (size_t)(q0 + r) * HID + c;
        const uint32_t dst = sQP + (r * LDATT + c) * 2;
        cp16(dst, src); cp16(dst + 16, src + 8);
        cp16(dst + 32, src + 16); cp16(dst + 48, src + 24);
    }
    load_kv(0, 0);
    load_kv(1, 1);
    load_kv(2, 2);

    mb_wait(mb + 0, 0);

    uint32_t qf[4][4];
    #pragma unroll
    for (int k4 = 0; k4 < 4; k4++) {
        const int kb = k4 * 16 + 2 * t4;
        qf[k4][0] = ld32s(&QP[rw * LDATT + kb]);
        qf[k4][1] = ld32s(&QP[(rw + 8) * LDATT + kb]);
        qf[k4][2] = ld32s(&QP[rw * LDATT + kb + 8]);
        qf[k4][3] = ld32s(&QP[(rw + 8) * LDATT + kb + 8]);
    }

    float m0 = -1e30f, m1 = -1e30f, l0 = 0.f, l1 = 0.f;
    float oacc[8][4];
    #pragma unroll
    for (int nf = 0; nf < 8; nf++)
        #pragma unroll
        for (int j = 0; j < 4; j++) oacc[nf][j] = 0.f;

    const int brow = (lane & 7) + ((lane >> 4) & 1) * 8;
    const int bkof = ((lane >> 3) & 1) * 8;

    int cph = 0, pph = 0;

    for (int kt = 0; kt < 32; kt++) {
        {
            const int tp = kt + 3;
            if (tp < 32) {
                const int ps = tp & 3;
                if (tp > 3) mb_wait(mb + 32 + ps * 8, pph);
                load_kv(tp, ps);
                if (tp > 3 && ps == 3) pph ^= 1;
            }
        }

        const int cs = kt & 3;
        mb_wait(mb + cs * 8, cph);

        const uint32_t sKc = sK + (uint32_t)cs * KVST * 2;
        const uint32_t sVc = sV + (uint32_t)cs * KVST * 2;

        float sacc[8][4];
        #pragma unroll
        for (int nf = 0; nf < 8; nf++)
            #pragma unroll
            for (int j = 0; j < 4; j++) sacc[nf][j] = 0.f;

        #pragma unroll
        for (int k4 = 0; k4 < 4; k4++) {
            const int kb0 = k4 * 16;
            #pragma unroll
            for (int nfp = 0; nfp < 4; nfp++) {
                uint32_t bfr[4];
                ldsm_x4(bfr, sKc + ((nfp * 16 + brow) * LDATT + kb0 + bkof) * 2);
                mma_bf16(sacc[2 * nfp],     qf[k4], bfr);
                mma_bf16(sacc[2 * nfp + 1], qf[k4], bfr + 2);
            }
        }

        #pragma unroll
        for (int ch = 0; ch < 2; ch++) {
            const int nfb = ch * 4;
            float mx0 = -1e30f, mx1 = -1e30f;
            #pragma unroll
            for (int nf = nfb; nf < nfb + 4; nf++) {
                mx0 = fmaxf(mx0, fmaxf(sacc[nf][0], sacc[nf][1]));
                mx1 = fmaxf(mx1, fmaxf(sacc[nf][2], sacc[nf][3]));
            }
            mx0 = fmaxf(mx0, __shfl_xor_sync(0xffffffffu, mx0, 1));
            mx0 = fmaxf(mx0, __shfl_xor_sync(0xffffffffu, mx0, 2));
            mx1 = fmaxf(mx1, __shfl_xor_sync(0xffffffffu, mx1, 1));
            mx1 = fmaxf(mx1, __shfl_xor_sync(0xffffffffu, mx1, 2));

            const float mn0 = fmaxf(m0, mx0 * SM_SCALE);
            const float mn1 = fmaxf(m1, mx1 * SM_SCALE);
            // corr-skip: if the running max did not change for ANY lane of the
            // warp, every corr is exactly 1.0 -> skip the rescale entirely.
            // Numerics are bit-identical (we only omit multiplies by 1.0).
            const bool same  = (mn0 == m0) & (mn1 == m1);
            const bool skip  = __all_sync(0xffffffffu, same);

            float rs0 = 0.f, rs1 = 0.f;
            #pragma unroll
            for (int nf = nfb; nf < nfb + 4; nf++) {
                sacc[nf][0] = ex2(fmaf(sacc[nf][0], SM_SCALE, -mn0));
                sacc[nf][1] = ex2(fmaf(sacc[nf][1], SM_SCALE, -mn0));
                sacc[nf][2] = ex2(fmaf(sacc[nf][2], SM_SCALE, -mn1));
                sacc[nf][3] = ex2(fmaf(sacc[nf][3], SM_SCALE, -mn1));
                rs0 += sacc[nf][0] + sacc[nf][1];
                rs1 += sacc[nf][2] + sacc[nf][3];
            }
            rs0 += __shfl_xor_sync(0xffffffffu, rs0, 1);
            rs0 += __shfl_xor_sync(0xffffffffu, rs0, 2);
            rs1 += __shfl_xor_sync(0xffffffffu, rs1, 1);
            rs1 += __shfl_xor_sync(0xffffffffu, rs1, 2);

            if (skip) {
                l0 += rs0;
                l1 += rs1;
            } else {
                const float corr0 = ex2(m0 - mn0), corr1 = ex2(m1 - mn1);
                l0 = l0 * corr0 + rs0;
                l1 = l1 * corr1 + rs1;
                #pragma unroll
                for (int nf = 0; nf < 8; nf++) {
                    oacc[nf][0] *= corr0; oacc[nf][1] *= corr0;
                    oacc[nf][2] *= corr1; oacc[nf][3] *= corr1;
                }
            }
            m0 = mn0; m1 = mn1;

            #pragma unroll
            for (int kh = 0; kh < 2; kh++) {
                const int k4 = 2 * ch + kh;
                uint32_t a[4];
                a[0] = packbf(sacc[2 * k4][0],     sacc[2 * k4][1]);
                a[1] = packbf(sacc[2 * k4][2],     sacc[2 * k4][3]);
                a[2] = packbf(sacc[2 * k4 + 1][0], sacc[2 * k4 + 1][1]);
                a[3] = packbf(sacc[2 * k4 + 1][2], sacc[2 * k4 + 1][3]);
                const int kk = k4 * 16;
                #pragma unroll
                for (int np = 0; np < 4; np++) {
                    uint32_t r[4];
                    const uint32_t addr = sVc +
                        ((kk + (lane & 15)) * LDATT + np * 16 + ((lane >> 4) << 3)) * 2;
                    ldsm_x4_t(r, addr);
                    mma_bf16(oacc[2 * np],     a, r);
                    mma_bf16(oacc[2 * np + 1], a, r + 2);
                }
            }
        }

        if (lane == 0) mb_arrive(mb + 32 + cs * 8);
        if (cs == 3) cph ^= 1;
    }

    const float inv0 = 1.f / l0, inv1 = 1.f / l1;
    #pragma unroll
    for (int nf = 0; nf < 8; nf++) {
        const int c = nf * 8 + 2 * t4;
        *(uint32_t*)&O[base + (size_t)(q0 + rw) * HID + c] =
            packbf(oacc[nf][0] * inv0, oacc[nf][1] * inv0);
        *(uint32_t*)&O[base + (size_t)(q0 + rw + 8) * HID + c] =
            packbf(oacc[nf][2] * inv1, oacc[nf][3] * inv1);
    }
}

// ---------------- launch -------------------------------------------------------
extern "C" void kernel_launch(void* const* d_in, const int* in_sizes, int n_in,
                              void* d_out, int out_size)
{
    const float* x    = (const float*)d_in[0];
    const float* Wq   = (const float*)d_in[1];
    const float* bq   = (const float*)d_in[2];
    const float* Wk   = (const float*)d_in[3];
    const float* bk   = (const float*)d_in[4];
    const float* Wv   = (const float*)d_in[5];
    const float* bv   = (const float*)d_in[6];
    const float* Wo   = (const float*)d_in[7];
    const float* bo   = (const float*)d_in[8];
    const float* ln_g = (const float*)d_in[9];
    const float* ln_b = (const float*)d_in[10];
    float* out = (float*)d_out;

    __nv_bfloat16 *xn_p, *q_p, *k_p, *v_p, *ctx_p, *wqkv_p, *wo_p;
    cudaGetSymbolAddress((void**)&xn_p,   g_xn);
    cudaGetSymbolAddress((void**)&q_p,    g_q);
    cudaGetSymbolAddress((void**)&k_p,    g_k);
    cudaGetSymbolAddress((void**)&v_p,    g_v);
    cudaGetSymbolAddress((void**)&ctx_p,  g_ctx);
    cudaGetSymbolAddress((void**)&wqkv_p, g_wqkv);
    cudaGetSymbolAddress((void**)&wo_p,   g_wo);

    cudaFuncSetAttribute(attn_mma,
        cudaFuncAttributeMaxDynamicSharedMemorySize, SMEM_ATTN);
    cudaFuncSetAttribute(mma_gemm,
        cudaFuncAttributeMaxDynamicSharedMemorySize, GEMM_SMEM);

    // 0) fused LayerNorm + weight conversion
    dim3 pg(4096, 2);
    prep_kernel<<<pg, 256>>>(x, ln_g, ln_b, xn_p,
                             (const float4*)Wq, (const float4*)Wk,
                             (const float4*)Wv, (const float4*)Wo,
                             (__nv_bfloat162*)wqkv_p, (__nv_bfloat162*)wo_p);

    // 1) fused QKV projection (one GEMM, N=3072)
    dim3 gq(3 * HID / 128, ROWS / 128);
    mma_gemm<<<gq, 256, GEMM_SMEM>>>(xn_p, wqkv_p, bq, bk, bv, nullptr,
                                     q_p, k_p, v_p, nullptr, 0);

    // 2) attention (free-running mbarrier pipeline + corr-skip)
    dim3 ag(SEQ / 128, HEADS, BATCH);
    attn_mma<<<ag, 256, SMEM_ATTN>>>(q_p, k_p, v_p, ctx_p);

    // 3) output projection + bias + residual (fp32 out)
    dim3 go(HID / 128, ROWS / 128);
    mma_gemm<<<go, 256, GEMM_SMEM>>>(ctx_p, wo_p, bo, bo, bo, x,
                                     nullptr, nullptr, nullptr, out, 1);
}

// round 16
// speedup vs baseline: 1.0880x; 1.0483x over previous
#include <cuda_runtime.h>
#include <cuda_bf16.h>
#include <cstdint>

#define HID    1024
#define SEQ    2048
#define BATCH  2
#define HEADS  16
#define HDIM   64
#define ROWS   (BATCH * SEQ)   // 4096

// ---------------- scratch (device globals; no allocations allowed) ----------
__device__ __nv_bfloat16 g_xn  [ROWS * HID];
__device__ __nv_bfloat16 g_q   [ROWS * HID];
__device__ __nv_bfloat16 g_k   [ROWS * HID];
__device__ __nv_bfloat16 g_v   [ROWS * HID];
__device__ __nv_bfloat16 g_ctx [ROWS * HID];
__device__ __nv_bfloat16 g_wqkv[3 * HID * HID];
__device__ __nv_bfloat16 g_wo  [HID * HID];

// ---------------- helpers ----------------------------------------------------
__device__ __forceinline__ uint32_t smem_u32(const void* p) {
    return (uint32_t)__cvta_generic_to_shared(p);
}
__device__ __forceinline__ void cp16(uint32_t dst, const void* src) {
    asm volatile("cp.async.cg.shared.global [%0], [%1], 16;" :: "r"(dst), "l"(src));
}
#define CP_COMMIT() asm volatile("cp.async.commit_group;")
#define CP_WAIT0()  asm volatile("cp.async.wait_group 0;")
#define CP_WAIT1()  asm volatile("cp.async.wait_group 1;")

__device__ __forceinline__ void mma_bf16(float* c, const uint32_t* a, const uint32_t* b) {
    asm volatile(
        "mma.sync.aligned.m16n8k16.row.col.f32.bf16.bf16.f32 "
        "{%0,%1,%2,%3}, {%4,%5,%6,%7}, {%8,%9}, {%0,%1,%2,%3};"
        : "+f"(c[0]), "+f"(c[1]), "+f"(c[2]), "+f"(c[3])
        : "r"(a[0]), "r"(a[1]), "r"(a[2]), "r"(a[3]), "r"(b[0]), "r"(b[1]));
}
__device__ __forceinline__ void ldsm_x4(uint32_t* r, uint32_t addr) {
    asm volatile("ldmatrix.sync.aligned.m8n8.x4.shared.b16 {%0,%1,%2,%3}, [%4];"
        : "=r"(r[0]), "=r"(r[1]), "=r"(r[2]), "=r"(r[3]) : "r"(addr));
}
__device__ __forceinline__ void ldsm_x4_t(uint32_t* r, uint32_t addr) {
    asm volatile("ldmatrix.sync.aligned.m8n8.x4.trans.shared.b16 {%0,%1,%2,%3}, [%4];"
        : "=r"(r[0]), "=r"(r[1]), "=r"(r[2]), "=r"(r[3]) : "r"(addr));
}
__device__ __forceinline__ uint32_t ld32s(const __nv_bfloat16* p) {
    return *(const uint32_t*)p;
}
__device__ __forceinline__ uint32_t packbf(float lo, float hi) {
    __nv_bfloat162 t = __floats2bfloat162_rn(lo, hi);
    return *(uint32_t*)&t;
}
__device__ __forceinline__ float ex2(float x) {
    float y;
    asm("ex2.approx.ftz.f32 %0, %1;" : "=f"(y) : "f"(x));
    return y;
}
// ---- mbarrier helpers --------------------------------------------------------
__device__ __forceinline__ void mb_init(uint32_t mbar, uint32_t cnt) {
    asm volatile("mbarrier.init.shared.b64 [%0], %1;" :: "r"(mbar), "r"(cnt) : "memory");
}
__device__ __forceinline__ void mb_arrive(uint32_t mbar) {
    asm volatile("mbarrier.arrive.shared.b64 _, [%0];" :: "r"(mbar) : "memory");
}
__device__ __forceinline__ void cp_async_mb_arrive(uint32_t mbar) {
    asm volatile("cp.async.mbarrier.arrive.noinc.shared.b64 [%0];" :: "r"(mbar) : "memory");
}
__device__ __forceinline__ void mb_wait(uint32_t mbar, uint32_t parity) {
    asm volatile(
        "{\n\t.reg .pred P;\n\t"
        "W_%=:\n\t"
        "mbarrier.try_wait.parity.acquire.cta.shared::cta.b64 P, [%0], %1, 0x989680;\n\t"
        "@P bra D_%=;\n\t"
        "bra W_%=;\n\t"
        "D_%=:\n\t}"
        :: "r"(mbar), "r"(parity) : "memory");
}

// ---------------- fused weight-convert + LayerNorm ----------------------------
__global__ __launch_bounds__(256) void prep_kernel(
    const float* __restrict__ x, const float* __restrict__ lg,
    const float* __restrict__ lb, __nv_bfloat16* __restrict__ xn,
    const float4* __restrict__ s0, const float4* __restrict__ s1,
    const float4* __restrict__ s2, const float4* __restrict__ s3,
    __nv_bfloat162* __restrict__ dqkv, __nv_bfloat162* __restrict__ dwo)
{
    const int tid = threadIdx.x;
    if (blockIdx.y == 1) {
        const int i = blockIdx.x * 256 + tid;
        const int mat = i >> 18;
        const int j = i & 262143;
        const float4* src = (mat == 0) ? s0 : (mat == 1) ? s1 : (mat == 2) ? s2 : s3;
        __nv_bfloat162* d = (mat == 3) ? dwo : dqkv + (size_t)mat * (HID * HID / 2);
        const float4 v = src[j];
        d[2 * j + 0] = __floats2bfloat162_rn(v.x, v.y);
        d[2 * j + 1] = __floats2bfloat162_rn(v.z, v.w);
        return;
    }
    __shared__ float red[16];
    const int row = blockIdx.x;
    const float4 v = *(const float4*)(x + (size_t)row * HID + tid * 4);

    float s1v = v.x + v.y + v.z + v.w;
    float s2v = v.x * v.x + v.y * v.y + v.z * v.z + v.w * v.w;
    #pragma unroll
    for (int off = 16; off; off >>= 1) {
        s1v += __shfl_xor_sync(0xffffffffu, s1v, off);
        s2v += __shfl_xor_sync(0xffffffffu, s2v, off);
    }
    const int warp = tid >> 5, lane = tid & 31;
    if (lane == 0) { red[warp] = s1v; red[warp + 8] = s2v; }
    __syncthreads();
    if (tid < 32) {
        float a  = (lane < 8) ? red[lane]     : 0.f;
        float b2 = (lane < 8) ? red[lane + 8] : 0.f;
        #pragma unroll
        for (int off = 4; off; off >>= 1) {
            a  += __shfl_xor_sync(0xffffffffu, a,  off);
            b2 += __shfl_xor_sync(0xffffffffu, b2, off);
        }
        if (lane == 0) { red[0] = a; red[1] = b2; }
    }
    __syncthreads();
    const float mu  = red[0] * (1.f / HID);
    const float var = red[1] * (1.f / HID) - mu * mu;
    const float rs  = rsqrtf(var + 1e-5f);

    const float4 gv = *(const float4*)(lg + tid * 4);
    const float4 bv = *(const float4*)(lb + tid * 4);
    __nv_bfloat162* o = (__nv_bfloat162*)(xn + (size_t)row * HID + tid * 4);
    o[0] = __floats2bfloat162_rn((v.x - mu) * rs * gv.x + bv.x,
                                 (v.y - mu) * rs * gv.y + bv.y);
    o[1] = __floats2bfloat162_rn((v.z - mu) * rs * gv.z + bv.z,
                                 (v.w - mu) * rs * gv.w + bv.w);
}

// ---------------- bf16 mma GEMM: free-running mbarrier pipeline ---------------
// 128x128x64 k-steps, 8 warps (2x4), warp tile 64x32, m16n8k16, 3 stages.
// No __syncthreads / wait_group in the mainloop: full[s] armed by 256 .noinc
// cp.async arrivals, empty[s] armed by one arrive per warp (warps drift).
#define LDK   72
#define TMAT  (128 * LDK)
#define TSTG  (2 * TMAT)
#define GEMM_SMEM (3 * TSTG * 2)

__global__ __launch_bounds__(256, 2) void mma_gemm(
    const __nv_bfloat16* __restrict__ A, const __nv_bfloat16* __restrict__ W,
    const float* __restrict__ b0p, const float* __restrict__ b1p,
    const float* __restrict__ b2p, const float* __restrict__ resid,
    __nv_bfloat16* __restrict__ C0, __nv_bfloat16* __restrict__ C1,
    __nv_bfloat16* __restrict__ C2, float* __restrict__ Cf, int out_fp32)
{
    extern __shared__ __nv_bfloat16 gsm[];
    __shared__ uint64_t gmb[6];          // full[0..2], empty[0..2]
    const int tid  = threadIdx.x;
    const int lane = tid & 31;
    const int wid  = tid >> 5;
    const int wm   = (wid >> 2) * 64;
    const int wn   = (wid & 3) * 32;
    const int row0 = blockIdx.y * 128, col0 = blockIdx.x * 128;
    const int g    = lane >> 2;
    const int t4   = lane & 3;

    const uint32_t s0 = smem_u32(gsm);
    const uint32_t mb = smem_u32(gmb);   // full(s)=mb+s*8 ; empty(s)=mb+24+s*8

    if (tid == 0) {
        #pragma unroll
        for (int s = 0; s < 3; s++) {
            mb_init(mb + s * 8, 256);      // full: one .noinc arrive per thread
            mb_init(mb + 24 + s * 8, 8);   // empty: one arrive per warp
        }
    }
    __syncthreads();

    auto load_chunk = [&](int kc, int stg) {
        const uint32_t sA = s0 + stg * TSTG * 2;
        const uint32_t sB = sA + TMAT * 2;
        const int kcol = kc * 64;
        #pragma unroll
        for (int it = 0; it < 4; it++) {
            const int id = it * 256 + tid;
            const int r = id >> 3;
            const int c = id & 7;
            const uint32_t off = (uint32_t)(r * LDK + c * 8) * 2;
            cp16(sA + off, A + (size_t)(row0 + r) * HID + kcol + c * 8);
            cp16(sB + off, W + (size_t)(col0 + r) * HID + kcol + c * 8);
        }
        cp_async_mb_arrive(mb + stg * 8);
    };

    float acc[4][4][4];
    #pragma unroll
    for (int i = 0; i < 4; i++)
        #pragma unroll
        for (int j = 0; j < 4; j++)
            #pragma unroll
            for (int r = 0; r < 4; r++) acc[i][j][r] = 0.f;

    load_chunk(0, 0);
    load_chunk(1, 1);

    const int arow = (lane & 7) + ((lane >> 3) & 1) * 8;
    const int akof = (lane >> 4) * 8;
    const int brow = (lane & 7) + ((lane >> 4) & 1) * 8;
    const int bkof = ((lane >> 3) & 1) * 8;

    int cph = 0, pph = 0;

    for (int kc = 0; kc < 16; kc++) {
        // producer: prefetch chunk kc+2 into the stage freed by chunk kc-1
        {
            const int tp = kc + 2;
            if (tp < 16) {
                const int ps = tp % 3;
                if (tp > 2) mb_wait(mb + 24 + ps * 8, pph);
                load_chunk(tp, ps);
                if (tp > 2 && ps == 2) pph ^= 1;
            }
        }

        // consumer: wait data for chunk kc
        const int cs = kc % 3;
        mb_wait(mb + cs * 8, cph);

        const uint32_t sAc = s0 + cs * TSTG * 2;
        const uint32_t sBc = sAc + TMAT * 2;
        #pragma unroll
        for (int kk = 0; kk < 64; kk += 16) {
            uint32_t af[4][4], bf[2][4];
            #pragma unroll
            for (int mf = 0; mf < 4; mf++)
                ldsm_x4(af[mf], sAc + ((wm + mf * 16 + arow) * LDK + kk + akof) * 2);
            #pragma unroll
            for (int nfp = 0; nfp < 2; nfp++)
                ldsm_x4(bf[nfp], sBc + ((wn + nfp * 16 + brow) * LDK + kk + bkof) * 2);
            #pragma unroll
            for (int mf = 0; mf < 4; mf++)
                #pragma unroll
                for (int nfp = 0; nfp < 2; nfp++) {
                    mma_bf16(acc[mf][2 * nfp],     af[mf], bf[nfp]);
                    mma_bf16(acc[mf][2 * nfp + 1], af[mf], bf[nfp] + 2);
                }
        }

        if (lane == 0) mb_arrive(mb + 24 + cs * 8);
        if (cs == 2) cph ^= 1;
    }

    const int sel  = col0 >> 10;
    const int colL = col0 & 1023;
    const float* bias = (sel == 0) ? b0p : (sel == 1) ? b1p : b2p;
    __nv_bfloat16* Cb = (sel == 0) ? C0 : (sel == 1) ? C1 : C2;
    const int t2 = t4 * 2;
    #pragma unroll
    for (int mf = 0; mf < 4; mf++) {
        #pragma unroll
        for (int nf = 0; nf < 4; nf++) {
            const int r = row0 + wm + mf * 16 + g;
            const int c = colL + wn + nf * 8 + t2;
            const float2 bb = *(const float2*)&bias[c];
            float o00 = acc[mf][nf][0] + bb.x, o01 = acc[mf][nf][1] + bb.y;
            float o10 = acc[mf][nf][2] + bb.x, o11 = acc[mf][nf][3] + bb.y;
            if (out_fp32) {
                const float2 r0v = *(const float2*)&resid[(size_t)r * HID + c];
                const float2 r1v = *(const float2*)&resid[(size_t)(r + 8) * HID + c];
                float2 a0 = { o00 + r0v.x, o01 + r0v.y };
                float2 a1 = { o10 + r1v.x, o11 + r1v.y };
                *(float2*)&Cf[(size_t)r * HID + c] = a0;
                *(float2*)&Cf[(size_t)(r + 8) * HID + c] = a1;
            } else {
                *(uint32_t*)&Cb[(size_t)r * HID + c] = packbf(o00, o01);
                *(uint32_t*)&Cb[(size_t)(r + 8) * HID + c] = packbf(o10, o11);
            }
        }
    }
}

// ---------------- Flash attention: mbarrier pipeline + corr-skip --------------
#define LDATT 72
#define NSTG  4
#define KVST  (64 * LDATT)
#define SMEM_ATTN ((128 * LDATT + 2 * NSTG * KVST) * 2)   // 92160 B
#define SM_SCALE 0.18033688011112042f                     // 0.125 * log2(e)

__global__ __launch_bounds__(256, 2) void attn_mma(
    const __nv_bfloat16* __restrict__ Q, const __nv_bfloat16* __restrict__ K,
    const __nv_bfloat16* __restrict__ V, __nv_bfloat16* __restrict__ O)
{
    extern __shared__ __nv_bfloat16 sm[];
    __nv_bfloat16* QP = sm;
    __nv_bfloat16* Ks = sm + 128 * LDATT;
    __nv_bfloat16* Vs = Ks + NSTG * KVST;
    __shared__ uint64_t mbars[2 * NSTG];

    const int tid  = threadIdx.x;
    const int lane = tid & 31;
    const int wid  = tid >> 5;
    const int g    = lane >> 2;
    const int t4   = lane & 3;
    const int q0   = blockIdx.x << 7;
    const size_t base = (size_t)blockIdx.z * SEQ * HID + (size_t)blockIdx.y * HDIM;
    const __nv_bfloat16* Qb = Q + base;
    const __nv_bfloat16* Kb = K + base;
    const __nv_bfloat16* Vb = V + base;
    const int rw = wid * 16 + g;

    const uint32_t sQP = smem_u32(QP);
    const uint32_t sK  = smem_u32(Ks);
    const uint32_t sV  = smem_u32(Vs);
    const uint32_t mb  = smem_u32(mbars);

    if (tid == 0) {
        #pragma unroll
        for (int s = 0; s < NSTG; s++) {
            mb_init(mb + s * 8, 256);
            mb_init(mb + 32 + s * 8, 8);
        }
    }
    __syncthreads();

    auto load_kv = [&](int kt, int stg) {
        const int k0n = kt << 6;
        const uint32_t so = (uint32_t)stg * KVST * 2;
        const int r = tid >> 2, c = (tid & 3) * 16;
        const __nv_bfloat16* ksrc = Kb + (size_t)(k0n + r) * HID + c;
        const __nv_bfloat16* vsrc = Vb + (size_t)(k0n + r) * HID + c;
        const uint32_t kd = sK + so + (r * LDATT + c) * 2;
        const uint32_t vd = sV + so + (r * LDATT + c) * 2;
        cp16(kd, ksrc); cp16(kd + 16, ksrc + 8);
        cp16(vd, vsrc); cp16(vd + 16, vsrc + 8);
        cp_async_mb_arrive(mb + stg * 8);
    };

    {
        const int r = tid >> 1, c = (tid & 1) * 32;
        const __nv_bfloat16* src = Qb + (size_t)(q0 + r) * HID + c;
        const uint32_t dst = sQP + (r * LDATT + c) * 2;
        cp16(dst, src); cp16(dst + 16, src + 8);
        cp16(dst + 32, src + 16); cp16(dst + 48, src + 24);
    }
    load_kv(0, 0);
    load_kv(1, 1);
    load_kv(2, 2);

    mb_wait(mb + 0, 0);

    uint32_t qf[4][4];
    #pragma unroll
    for (int k4 = 0; k4 < 4; k4++) {
        const int kb = k4 * 16 + 2 * t4;
        qf[k4][0] = ld32s(&QP[rw * LDATT + kb]);
        qf[k4][1] = ld32s(&QP[(rw + 8) * LDATT + kb]);
        qf[k4][2] = ld32s(&QP[rw * LDATT + kb + 8]);
        qf[k4][3] = ld32s(&QP[(rw + 8) * LDATT + kb + 8]);
    }

    float m0 = -1e30f, m1 = -1e30f, l0 = 0.f, l1 = 0.f;
    float oacc[8][4];
    #pragma unroll
    for (int nf = 0; nf < 8; nf++)
        #pragma unroll
        for (int j = 0; j < 4; j++) oacc[nf][j] = 0.f;

    const int brow = (lane & 7) + ((lane >> 4) & 1) * 8;
    const int bkof = ((lane >> 3) & 1) * 8;

    int cph = 0, pph = 0;

    for (int kt = 0; kt < 32; kt++) {
        {
            const int tp = kt + 3;
            if (tp < 32) {
                const int ps = tp & 3;
                if (tp > 3) mb_wait(mb + 32 + ps * 8, pph);
                load_kv(tp, ps);
                if (tp > 3 && ps == 3) pph ^= 1;
            }
        }

        const int cs = kt & 3;
        mb_wait(mb + cs * 8, cph);

        const uint32_t sKc = sK + (uint32_t)cs * KVST * 2;
        const uint32_t sVc = sV + (uint32_t)cs * KVST * 2;

        float sacc[8][4];
        #pragma unroll
        for (int nf = 0; nf < 8; nf++)
            #pragma unroll
            for (int j = 0; j < 4; j++) sacc[nf][j] = 0.f;

        #pragma unroll
        for (int k4 = 0; k4 < 4; k4++) {
            const int kb0 = k4 * 16;
            #pragma unroll
            for (int nfp = 0; nfp < 4; nfp++) {
                uint32_t bfr[4];
                ldsm_x4(bfr, sKc + ((nfp * 16 + brow) * LDATT + kb0 + bkof) * 2);
                mma_bf16(sacc[2 * nfp],     qf[k4], bfr);
                mma_bf16(sacc[2 * nfp + 1], qf[k4], bfr + 2);
            }
        }

        #pragma unroll
        for (int ch = 0; ch < 2; ch++) {
            const int nfb = ch * 4;
            float mx0 = -1e30f, mx1 = -1e30f;
            #pragma unroll
            for (int nf = nfb; nf < nfb + 4; nf++) {
                mx0 = fmaxf(mx0, fmaxf(sacc[nf][0], sacc[nf][1]));
                mx1 = fmaxf(mx1, fmaxf(sacc[nf][2], sacc[nf][3]));
            }
            mx0 = fmaxf(mx0, __shfl_xor_sync(0xffffffffu, mx0, 1));
            mx0 = fmaxf(mx0, __shfl_xor_sync(0xffffffffu, mx0, 2));
            mx1 = fmaxf(mx1, __shfl_xor_sync(0xffffffffu, mx1, 1));
            mx1 = fmaxf(mx1, __shfl_xor_sync(0xffffffffu, mx1, 2));

            const float mn0 = fmaxf(m0, mx0 * SM_SCALE);
            const float mn1 = fmaxf(m1, mx1 * SM_SCALE);
            const bool same  = (mn0 == m0) & (mn1 == m1);
            const bool skip  = __all_sync(0xffffffffu, same);

            float rs0 = 0.f, rs1 = 0.f;
            #pragma unroll
            for (int nf = nfb; nf < nfb + 4; nf++) {
                sacc[nf][0] = ex2(fmaf(sacc[nf][0], SM_SCALE, -mn0));
                sacc[nf][1] = ex2(fmaf(sacc[nf][1], SM_SCALE, -mn0));
                sacc[nf][2] = ex2(fmaf(sacc[nf][2], SM_SCALE, -mn1));
                sacc[nf][3] = ex2(fmaf(sacc[nf][3], SM_SCALE, -mn1));
                rs0 += sacc[nf][0] + sacc[nf][1];
                rs1 += sacc[nf][2] + sacc[nf][3];
            }
            rs0 += __shfl_xor_sync(0xffffffffu, rs0, 1);
            rs0 += __shfl_xor_sync(0xffffffffu, rs0, 2);
            rs1 += __shfl_xor_sync(0xffffffffu, rs1, 1);
            rs1 += __shfl_xor_sync(0xffffffffu, rs1, 2);

            if (skip) {
                l0 += rs0;
                l1 += rs1;
            } else {
                const float corr0 = ex2(m0 - mn0), corr1 = ex2(m1 - mn1);
                l0 = l0 * corr0 + rs0;
                l1 = l1 * corr1 + rs1;
                #pragma unroll
                for (int nf = 0; nf < 8; nf++) {
                    oacc[nf][0] *= corr0; oacc[nf][1] *= corr0;
                    oacc[nf][2] *= corr1; oacc[nf][3] *= corr1;
                }
            }
            m0 = mn0; m1 = mn1;

            #pragma unroll
            for (int kh = 0; kh < 2; kh++) {
                const int k4 = 2 * ch + kh;
                uint32_t a[4];
                a[0] = packbf(sacc[2 * k4][0],     sacc[2 * k4][1]);
                a[1] = packbf(sacc[2 * k4][2],     sacc[2 * k4][3]);
                a[2] = packbf(sacc[2 * k4 + 1][0], sacc[2 * k4 + 1][1]);
                a[3] = packbf(sacc[2 * k4 + 1][2], sacc[2 * k4 + 1][3]);
                const int kk = k4 * 16;
                #pragma unroll
                for (int np = 0; np < 4; np++) {
                    uint32_t r[4];
                    const uint32_t addr = sVc +
                        ((kk + (lane & 15)) * LDATT + np * 16 + ((lane >> 4) << 3)) * 2;
                    ldsm_x4_t(r, addr);
                    mma_bf16(oacc[2 * np],     a, r);
                    mma_bf16(oacc[2 * np + 1], a, r + 2);
                }
            }
        }

        if (lane == 0) mb_arrive(mb + 32 + cs * 8);
        if (cs == 3) cph ^= 1;
    }

    const float inv0 = 1.f / l0, inv1 = 1.f / l1;
    #pragma unroll
    for (int nf = 0; nf < 8; nf++) {
        const int c = nf * 8 + 2 * t4;
        *(uint32_t*)&O[base + (size_t)(q0 + rw) * HID + c] =
            packbf(oacc[nf][0] * inv0, oacc[nf][1] * inv0);
        *(uint32_t*)&O[base + (size_t)(q0 + rw + 8) * HID + c] =
            packbf(oacc[nf][2] * inv1, oacc[nf][3] * inv1);
    }
}

// ---------------- launch -------------------------------------------------------
extern "C" void kernel_launch(void* const* d_in, const int* in_sizes, int n_in,
                              void* d_out, int out_size)
{
    const float* x    = (const float*)d_in[0];
    const float* Wq   = (const float*)d_in[1];
    const float* bq   = (const float*)d_in[2];
    const float* Wk   = (const float*)d_in[3];
    const float* bk   = (const float*)d_in[4];
    const float* Wv   = (const float*)d_in[5];
    const float* bv   = (const float*)d_in[6];
    const float* Wo   = (const float*)d_in[7];
    const float* bo   = (const float*)d_in[8];
    const float* ln_g = (const float*)d_in[9];
    const float* ln_b = (const float*)d_in[10];
    float* out = (float*)d_out;

    __nv_bfloat16 *xn_p, *q_p, *k_p, *v_p, *ctx_p, *wqkv_p, *wo_p;
    cudaGetSymbolAddress((void**)&xn_p,   g_xn);
    cudaGetSymbolAddress((void**)&q_p,    g_q);
    cudaGetSymbolAddress((void**)&k_p,    g_k);
    cudaGetSymbolAddress((void**)&v_p,    g_v);
    cudaGetSymbolAddress((void**)&ctx_p,  g_ctx);
    cudaGetSymbolAddress((void**)&wqkv_p, g_wqkv);
    cudaGetSymbolAddress((void**)&wo_p,   g_wo);

    cudaFuncSetAttribute(attn_mma,
        cudaFuncAttributeMaxDynamicSharedMemorySize, SMEM_ATTN);
    cudaFuncSetAttribute(mma_gemm,
        cudaFuncAttributeMaxDynamicSharedMemorySize, GEMM_SMEM);

    // 0) fused LayerNorm + weight conversion
    dim3 pg(4096, 2);
    prep_kernel<<<pg, 256>>>(x, ln_g, ln_b, xn_p,
                             (const float4*)Wq, (const float4*)Wk,
                             (const float4*)Wv, (const float4*)Wo,
                             (__nv_bfloat162*)wqkv_p, (__nv_bfloat162*)wo_p);

    // 1) fused QKV projection (one GEMM, N=3072)
    dim3 gq(3 * HID / 128, ROWS / 128);
    mma_gemm<<<gq, 256, GEMM_SMEM>>>(xn_p, wqkv_p, bq, bk, bv, nullptr,
                                     q_p, k_p, v_p, nullptr, 0);

    // 2) attention (free-running mbarrier pipeline + corr-skip)
    dim3 ag(SEQ / 128, HEADS, BATCH);
    attn_mma<<<ag, 256, SMEM_ATTN>>>(q_p, k_p, v_p, ctx_p);

    // 3) output projection + bias + residual (fp32 out)
    dim3 go(HID / 128, ROWS / 128);
    mma_gemm<<<go, 256, GEMM_SMEM>>>(ctx_p, wo_p, bo, bo, bo, x,
                                     nullptr, nullptr, nullptr, out, 1);
}

// round 17
// speedup vs baseline: 1.0912x; 1.0029x over previous
#include <cuda_runtime.h>
#include <cuda_bf16.h>
#include <cstdint>

#define HID    1024
#define SEQ    2048
#define BATCH  2
#define HEADS  16
#define HDIM   64
#define ROWS   (BATCH * SEQ)   // 4096

// ---------------- scratch (device globals; no allocations allowed) ----------
__device__ __nv_bfloat16 g_xn  [ROWS * HID];
__device__ __nv_bfloat16 g_q   [ROWS * HID];
__device__ __nv_bfloat16 g_k   [ROWS * HID];
__device__ __nv_bfloat16 g_v   [ROWS * HID];
__device__ __nv_bfloat16 g_ctx [ROWS * HID];
__device__ __nv_bfloat16 g_wqkv[3 * HID * HID];
__device__ __nv_bfloat16 g_wo  [HID * HID];

// ---------------- helpers ----------------------------------------------------
__device__ __forceinline__ uint32_t smem_u32(const void* p) {
    return (uint32_t)__cvta_generic_to_shared(p);
}
__device__ __forceinline__ void cp16(uint32_t dst, const void* src) {
    asm volatile("cp.async.cg.shared.global [%0], [%1], 16;" :: "r"(dst), "l"(src));
}

__device__ __forceinline__ void mma_bf16(float* c, const uint32_t* a, const uint32_t* b) {
    asm volatile(
        "mma.sync.aligned.m16n8k16.row.col.f32.bf16.bf16.f32 "
        "{%0,%1,%2,%3}, {%4,%5,%6,%7}, {%8,%9}, {%0,%1,%2,%3};"
        : "+f"(c[0]), "+f"(c[1]), "+f"(c[2]), "+f"(c[3])
        : "r"(a[0]), "r"(a[1]), "r"(a[2]), "r"(a[3]), "r"(b[0]), "r"(b[1]));
}
__device__ __forceinline__ void ldsm_x4(uint32_t* r, uint32_t addr) {
    asm volatile("ldmatrix.sync.aligned.m8n8.x4.shared.b16 {%0,%1,%2,%3}, [%4];"
        : "=r"(r[0]), "=r"(r[1]), "=r"(r[2]), "=r"(r[3]) : "r"(addr));
}
__device__ __forceinline__ void ldsm_x4_t(uint32_t* r, uint32_t addr) {
    asm volatile("ldmatrix.sync.aligned.m8n8.x4.trans.shared.b16 {%0,%1,%2,%3}, [%4];"
        : "=r"(r[0]), "=r"(r[1]), "=r"(r[2]), "=r"(r[3]) : "r"(addr));
}
__device__ __forceinline__ uint32_t ld32s(const __nv_bfloat16* p) {
    return *(const uint32_t*)p;
}
__device__ __forceinline__ uint32_t packbf(float lo, float hi) {
    __nv_bfloat162 t = __floats2bfloat162_rn(lo, hi);
    return *(uint32_t*)&t;
}
__device__ __forceinline__ float ex2(float x) {
    float y;
    asm("ex2.approx.ftz.f32 %0, %1;" : "=f"(y) : "f"(x));
    return y;
}
// ---- mbarrier helpers --------------------------------------------------------
__device__ __forceinline__ void mb_init(uint32_t mbar, uint32_t cnt) {
    asm volatile("mbarrier.init.shared.b64 [%0], %1;" :: "r"(mbar), "r"(cnt) : "memory");
}
__device__ __forceinline__ void mb_arrive(uint32_t mbar) {
    asm volatile("mbarrier.arrive.shared.b64 _, [%0];" :: "r"(mbar) : "memory");
}
__device__ __forceinline__ void cp_async_mb_arrive(uint32_t mbar) {
    asm volatile("cp.async.mbarrier.arrive.noinc.shared.b64 [%0];" :: "r"(mbar) : "memory");
}
__device__ __forceinline__ void mb_wait(uint32_t mbar, uint32_t parity) {
    asm volatile(
        "{\n\t.reg .pred P;\n\t"
        "W_%=:\n\t"
        "mbarrier.try_wait.parity.acquire.cta.shared::cta.b64 P, [%0], %1, 0x989680;\n\t"
        "@P bra D_%=;\n\t"
        "bra W_%=;\n\t"
        "D_%=:\n\t}"
        :: "r"(mbar), "r"(parity) : "memory");
}

// ---------------- fused weight-convert + LayerNorm ----------------------------
__global__ __launch_bounds__(256) void prep_kernel(
    const float* __restrict__ x, const float* __restrict__ lg,
    const float* __restrict__ lb, __nv_bfloat16* __restrict__ xn,
    const float4* __restrict__ s0, const float4* __restrict__ s1,
    const float4* __restrict__ s2, const float4* __restrict__ s3,
    __nv_bfloat162* __restrict__ dqkv, __nv_bfloat162* __restrict__ dwo)
{
    const int tid = threadIdx.x;
    if (blockIdx.y == 1) {
        const int i = blockIdx.x * 256 + tid;
        const int mat = i >> 18;
        const int j = i & 262143;
        const float4* src = (mat == 0) ? s0 : (mat == 1) ? s1 : (mat == 2) ? s2 : s3;
        __nv_bfloat162* d = (mat == 3) ? dwo : dqkv + (size_t)mat * (HID * HID / 2);
        const float4 v = src[j];
        d[2 * j + 0] = __floats2bfloat162_rn(v.x, v.y);
        d[2 * j + 1] = __floats2bfloat162_rn(v.z, v.w);
        return;
    }
    __shared__ float red[16];
    const int row = blockIdx.x;
    const float4 v = *(const float4*)(x + (size_t)row * HID + tid * 4);

    float s1v = v.x + v.y + v.z + v.w;
    float s2v = v.x * v.x + v.y * v.y + v.z * v.z + v.w * v.w;
    #pragma unroll
    for (int off = 16; off; off >>= 1) {
        s1v += __shfl_xor_sync(0xffffffffu, s1v, off);
        s2v += __shfl_xor_sync(0xffffffffu, s2v, off);
    }
    const int warp = tid >> 5, lane = tid & 31;
    if (lane == 0) { red[warp] = s1v; red[warp + 8] = s2v; }
    __syncthreads();
    if (tid < 32) {
        float a  = (lane < 8) ? red[lane]     : 0.f;
        float b2 = (lane < 8) ? red[lane + 8] : 0.f;
        #pragma unroll
        for (int off = 4; off; off >>= 1) {
            a  += __shfl_xor_sync(0xffffffffu, a,  off);
            b2 += __shfl_xor_sync(0xffffffffu, b2, off);
        }
        if (lane == 0) { red[0] = a; red[1] = b2; }
    }
    __syncthreads();
    const float mu  = red[0] * (1.f / HID);
    const float var = red[1] * (1.f / HID) - mu * mu;
    const float rs  = rsqrtf(var + 1e-5f);

    const float4 gv = *(const float4*)(lg + tid * 4);
    const float4 bv = *(const float4*)(lb + tid * 4);
    __nv_bfloat162* o = (__nv_bfloat162*)(xn + (size_t)row * HID + tid * 4);
    o[0] = __floats2bfloat162_rn((v.x - mu) * rs * gv.x + bv.x,
                                 (v.y - mu) * rs * gv.y + bv.y);
    o[1] = __floats2bfloat162_rn((v.z - mu) * rs * gv.z + bv.z,
                                 (v.w - mu) * rs * gv.w + bv.w);
}

// ---------------- bf16 mma GEMM: mbarrier pipeline, consumer-first ------------
// 128x128x64 k-steps, 8 warps (2x4), warp tile 64x32, m16n8k16, 3 stages.
// Mainloop order: wait full -> ldsm/mma -> prefetch (tensor-drain shadow) ->
// arrive empty. Schedule/parity identical to R16, just relocated.
#define LDK   72
#define TMAT  (128 * LDK)
#define TSTG  (2 * TMAT)
#define GEMM_SMEM (3 * TSTG * 2)

__global__ __launch_bounds__(256, 2) void mma_gemm(
    const __nv_bfloat16* __restrict__ A, const __nv_bfloat16* __restrict__ W,
    const float* __restrict__ b0p, const float* __restrict__ b1p,
    const float* __restrict__ b2p, const float* __restrict__ resid,
    __nv_bfloat16* __restrict__ C0, __nv_bfloat16* __restrict__ C1,
    __nv_bfloat16* __restrict__ C2, float* __restrict__ Cf, int out_fp32)
{
    extern __shared__ __nv_bfloat16 gsm[];
    __shared__ uint64_t gmb[6];          // full[0..2], empty[0..2]
    const int tid  = threadIdx.x;
    const int lane = tid & 31;
    const int wid  = tid >> 5;
    const int wm   = (wid >> 2) * 64;
    const int wn   = (wid & 3) * 32;
    const int row0 = blockIdx.y * 128, col0 = blockIdx.x * 128;
    const int g    = lane >> 2;
    const int t4   = lane & 3;

    const uint32_t s0 = smem_u32(gsm);
    const uint32_t mb = smem_u32(gmb);   // full(s)=mb+s*8 ; empty(s)=mb+24+s*8

    if (tid == 0) {
        #pragma unroll
        for (int s = 0; s < 3; s++) {
            mb_init(mb + s * 8, 256);      // full: one .noinc arrive per thread
            mb_init(mb + 24 + s * 8, 8);   // empty: one arrive per warp
        }
    }
    __syncthreads();

    auto load_chunk = [&](int kc, int stg) {
        const uint32_t sA = s0 + stg * TSTG * 2;
        const uint32_t sB = sA + TMAT * 2;
        const int kcol = kc * 64;
        #pragma unroll
        for (int it = 0; it < 4; it++) {
            const int id = it * 256 + tid;
            const int r = id >> 3;
            const int c = id & 7;
            const uint32_t off = (uint32_t)(r * LDK + c * 8) * 2;
            cp16(sA + off, A + (size_t)(row0 + r) * HID + kcol + c * 8);
            cp16(sB + off, W + (size_t)(col0 + r) * HID + kcol + c * 8);
        }
        cp_async_mb_arrive(mb + stg * 8);
    };

    float acc[4][4][4];
    #pragma unroll
    for (int i = 0; i < 4; i++)
        #pragma unroll
        for (int j = 0; j < 4; j++)
            #pragma unroll
            for (int r = 0; r < 4; r++) acc[i][j][r] = 0.f;

    load_chunk(0, 0);
    load_chunk(1, 1);

    const int arow = (lane & 7) + ((lane >> 3) & 1) * 8;
    const int akof = (lane >> 4) * 8;
    const int brow = (lane & 7) + ((lane >> 4) & 1) * 8;
    const int bkof = ((lane >> 3) & 1) * 8;

    int cph = 0, pph = 0;

    for (int kc = 0; kc < 16; kc++) {
        // consumer: wait data for chunk kc, then stream ldsm+mma
        const int cs = kc % 3;
        mb_wait(mb + cs * 8, cph);

        const uint32_t sAc = s0 + cs * TSTG * 2;
        const uint32_t sBc = sAc + TMAT * 2;
        #pragma unroll
        for (int kk = 0; kk < 64; kk += 16) {
            uint32_t af[4][4], bf[2][4];
            #pragma unroll
            for (int mf = 0; mf < 4; mf++)
                ldsm_x4(af[mf], sAc + ((wm + mf * 16 + arow) * LDK + kk + akof) * 2);
            #pragma unroll
            for (int nfp = 0; nfp < 2; nfp++)
                ldsm_x4(bf[nfp], sBc + ((wn + nfp * 16 + brow) * LDK + kk + bkof) * 2);
            #pragma unroll
            for (int mf = 0; mf < 4; mf++)
                #pragma unroll
                for (int nfp = 0; nfp < 2; nfp++) {
                    mma_bf16(acc[mf][2 * nfp],     af[mf], bf[nfp]);
                    mma_bf16(acc[mf][2 * nfp + 1], af[mf], bf[nfp] + 2);
                }
        }

        // producer: prefetch chunk kc+2 in the tensor-drain shadow
        {
            const int tp = kc + 2;
            if (tp < 16) {
                const int ps = tp % 3;
                if (tp > 2) mb_wait(mb + 24 + ps * 8, pph);
                load_chunk(tp, ps);
                if (tp > 2 && ps == 2) pph ^= 1;
            }
        }

        if (lane == 0) mb_arrive(mb + 24 + cs * 8);
        if (cs == 2) cph ^= 1;
    }

    const int sel  = col0 >> 10;
    const int colL = col0 & 1023;
    const float* bias = (sel == 0) ? b0p : (sel == 1) ? b1p : b2p;
    __nv_bfloat16* Cb = (sel == 0) ? C0 : (sel == 1) ? C1 : C2;
    const int t2 = t4 * 2;
    #pragma unroll
    for (int mf = 0; mf < 4; mf++) {
        #pragma unroll
        for (int nf = 0; nf < 4; nf++) {
            const int r = row0 + wm + mf * 16 + g;
            const int c = colL + wn + nf * 8 + t2;
            const float2 bb = *(const float2*)&bias[c];
            float o00 = acc[mf][nf][0] + bb.x, o01 = acc[mf][nf][1] + bb.y;
            float o10 = acc[mf][nf][2] + bb.x, o11 = acc[mf][nf][3] + bb.y;
            if (out_fp32) {
                const float2 r0v = *(const float2*)&resid[(size_t)r * HID + c];
                const float2 r1v = *(const float2*)&resid[(size_t)(r + 8) * HID + c];
                float2 a0 = { o00 + r0v.x, o01 + r0v.y };
                float2 a1 = { o10 + r1v.x, o11 + r1v.y };
                *(float2*)&Cf[(size_t)r * HID + c] = a0;
                *(float2*)&Cf[(size_t)(r + 8) * HID + c] = a1;
            } else {
                *(uint32_t*)&Cb[(size_t)r * HID + c] = packbf(o00, o01);
                *(uint32_t*)&Cb[(size_t)(r + 8) * HID + c] = packbf(o10, o11);
            }
        }
    }
}

// ---------------- Flash attention: mbarrier pipeline + corr-skip --------------
#define LDATT 72
#define NSTG  4
#define KVST  (64 * LDATT)
#define SMEM_ATTN ((128 * LDATT + 2 * NSTG * KVST) * 2)   // 92160 B
#define SM_SCALE 0.18033688011112042f                     // 0.125 * log2(e)

__global__ __launch_bounds__(256, 2) void attn_mma(
    const __nv_bfloat16* __restrict__ Q, const __nv_bfloat16* __restrict__ K,
    const __nv_bfloat16* __restrict__ V, __nv_bfloat16* __restrict__ O)
{
    extern __shared__ __nv_bfloat16 sm[];
    __nv_bfloat16* QP = sm;
    __nv_bfloat16* Ks = sm + 128 * LDATT;
    __nv_bfloat16* Vs = Ks + NSTG * KVST;
    __shared__ uint64_t mbars[2 * NSTG];

    const int tid  = threadIdx.x;
    const int lane = tid & 31;
    const int wid  = tid >> 5;
    const int g    = lane >> 2;
    const int t4   = lane & 3;
    const int q0   = blockIdx.x << 7;
    const size_t base = (size_t)blockIdx.z * SEQ * HID + (size_t)blockIdx.y * HDIM;
    const __nv_bfloat16* Qb = Q + base;
    const __nv_bfloat16* Kb = K + base;
    const __nv_bfloat16* Vb = V + base;
    const int rw = wid * 16 + g;

    const uint32_t sQP = smem_u32(QP);
    const uint32_t sK  = smem_u32(Ks);
    const uint32_t sV  = smem_u32(Vs);
    const uint32_t mb  = smem_u32(mbars);

    if (tid == 0) {
        #pragma unroll
        for (int s = 0; s < NSTG; s++) {
            mb_init(mb + s * 8, 256);
            mb_init(mb + 32 + s * 8, 8);
        }
    }
    __syncthreads();

    auto load_kv = [&](int kt, int stg) {
        const int k0n = kt << 6;
        const uint32_t so = (uint32_t)stg * KVST * 2;
        const int r = tid >> 2, c = (tid & 3) * 16;
        const __nv_bfloat16* ksrc = Kb + (size_t)(k0n + r) * HID + c;
        const __nv_bfloat16* vsrc = Vb + (size_t)(k0n + r) * HID + c;
        const uint32_t kd = sK + so + (r * LDATT + c) * 2;
        const uint32_t vd = sV + so + (r * LDATT + c) * 2;
        cp16(kd, ksrc); cp16(kd + 16, ksrc + 8);
        cp16(vd, vsrc); cp16(vd + 16, vsrc + 8);
        cp_async_mb_arrive(mb + stg * 8);
    };

    {
        const int r = tid >> 1, c = (tid & 1) * 32;
        const __nv_bfloat16* src = Qb + (size_t)(q0 + r) * HID + c;
        const uint32_t dst = sQP + (r * LDATT + c) * 2;
        cp16(dst, src); cp16(dst + 16, src + 8);
        cp16(dst + 32, src + 16); cp16(dst + 48, src + 24);
    }
    load_kv(0, 0);
    load_kv(1, 1);
    load_kv(2, 2);

    mb_wait(mb + 0, 0);

    uint32_t qf[4][4];
    #pragma unroll
    for (int k4 = 0; k4 < 4; k4++) {
        const int kb = k4 * 16 + 2 * t4;
        qf[k4][0] = ld32s(&QP[rw * LDATT + kb]);
        qf[k4][1] = ld32s(&QP[(rw + 8) * LDATT + kb]);
        qf[k4][2] = ld32s(&QP[rw * LDATT + kb + 8]);
        qf[k4][3] = ld32s(&QP[(rw + 8) * LDATT + kb + 8]);
    }

    float m0 = -1e30f, m1 = -1e30f, l0 = 0.f, l1 = 0.f;
    float oacc[8][4];
    #pragma unroll
    for (int nf = 0; nf < 8; nf++)
        #pragma unroll
        for (int j = 0; j < 4; j++) oacc[nf][j] = 0.f;

    const int brow = (lane & 7) + ((lane >> 4) & 1) * 8;
    const int bkof = ((lane >> 3) & 1) * 8;

    int cph = 0, pph = 0;

    for (int kt = 0; kt < 32; kt++) {
        {
            const int tp = kt + 3;
            if (tp < 32) {
                const int ps = tp & 3;
                if (tp > 3) mb_wait(mb + 32 + ps * 8, pph);
                load_kv(tp, ps);
                if (tp > 3 && ps == 3) pph ^= 1;
            }
        }

        const int cs = kt & 3;
        mb_wait(mb + cs * 8, cph);

        const uint32_t sKc = sK + (uint32_t)cs * KVST * 2;
        const uint32_t sVc = sV + (uint32_t)cs * KVST * 2;

        float sacc[8][4];
        #pragma unroll
        for (int nf = 0; nf < 8; nf++)
            #pragma unroll
            for (int j = 0; j < 4; j++) sacc[nf][j] = 0.f;

        #pragma unroll
        for (int k4 = 0; k4 < 4; k4++) {
            const int kb0 = k4 * 16;
            #pragma unroll
            for (int nfp = 0; nfp < 4; nfp++) {
                uint32_t bfr[4];
                ldsm_x4(bfr, sKc + ((nfp * 16 + brow) * LDATT + kb0 + bkof) * 2);
                mma_bf16(sacc[2 * nfp],     qf[k4], bfr);
                mma_bf16(sacc[2 * nfp + 1], qf[k4], bfr + 2);
            }
        }

        #pragma unroll
        for (int ch = 0; ch < 2; ch++) {
            const int nfb = ch * 4;
            float mx0 = -1e30f, mx1 = -1e30f;
            #pragma unroll
            for (int nf = nfb; nf < nfb + 4; nf++) {
                mx0 = fmaxf(mx0, fmaxf(sacc[nf][0], sacc[nf][1]));
                mx1 = fmaxf(mx1, fmaxf(sacc[nf][2], sacc[nf][3]));
            }
            mx0 = fmaxf(mx0, __shfl_xor_sync(0xffffffffu, mx0, 1));
            mx0 = fmaxf(mx0, __shfl_xor_sync(0xffffffffu, mx0, 2));
            mx1 = fmaxf(mx1, __shfl_xor_sync(0xffffffffu, mx1, 1));
            mx1 = fmaxf(mx1, __shfl_xor_sync(0xffffffffu, mx1, 2));

            const float mn0 = fmaxf(m0, mx0 * SM_SCALE);
            const float mn1 = fmaxf(m1, mx1 * SM_SCALE);
            const bool same  = (mn0 == m0) & (mn1 == m1);
            const bool skip  = __all_sync(0xffffffffu, same);

            float rs0 = 0.f, rs1 = 0.f;
            #pragma unroll
            for (int nf = nfb; nf < nfb + 4; nf++) {
                sacc[nf][0] = ex2(fmaf(sacc[nf][0], SM_SCALE, -mn0));
                sacc[nf][1] = ex2(fmaf(sacc[nf][1], SM_SCALE, -mn0));
                sacc[nf][2] = ex2(fmaf(sacc[nf][2], SM_SCALE, -mn1));
                sacc[nf][3] = ex2(fmaf(sacc[nf][3], SM_SCALE, -mn1));
                rs0 += sacc[nf][0] + sacc[nf][1];
                rs1 += sacc[nf][2] + sacc[nf][3];
            }
            rs0 += __shfl_xor_sync(0xffffffffu, rs0, 1);
            rs0 += __shfl_xor_sync(0xffffffffu, rs0, 2);
            rs1 += __shfl_xor_sync(0xffffffffu, rs1, 1);
            rs1 += __shfl_xor_sync(0xffffffffu, rs1, 2);

            if (skip) {
                l0 += rs0;
                l1 += rs1;
            } else {
                const float corr0 = ex2(m0 - mn0), corr1 = ex2(m1 - mn1);
                l0 = l0 * corr0 + rs0;
                l1 = l1 * corr1 + rs1;
                #pragma unroll
                for (int nf = 0; nf < 8; nf++) {
                    oacc[nf][0] *= corr0; oacc[nf][1] *= corr0;
                    oacc[nf][2] *= corr1; oacc[nf][3] *= corr1;
                }
            }
            m0 = mn0; m1 = mn1;

            #pragma unroll
            for (int kh = 0; kh < 2; kh++) {
                const int k4 = 2 * ch + kh;
                uint32_t a[4];
                a[0] = packbf(sacc[2 * k4][0],     sacc[2 * k4][1]);
                a[1] = packbf(sacc[2 * k4][2],     sacc[2 * k4][3]);
                a[2] = packbf(sacc[2 * k4 + 1][0], sacc[2 * k4 + 1][1]);
                a[3] = packbf(sacc[2 * k4 + 1][2], sacc[2 * k4 + 1][3]);
                const int kk = k4 * 16;
                #pragma unroll
                for (int np = 0; np < 4; np++) {
                    uint32_t r[4];
                    const uint32_t addr = sVc +
                        ((kk + (lane & 15)) * LDATT + np * 16 + ((lane >> 4) << 3)) * 2;
                    ldsm_x4_t(r, addr);
                    mma_bf16(oacc[2 * np],     a, r);
                    mma_bf16(oacc[2 * np + 1], a, r + 2);
                }
            }
        }

        if (lane == 0) mb_arrive(mb + 32 + cs * 8);
        if (cs == 3) cph ^= 1;
    }

    const float inv0 = 1.f / l0, inv1 = 1.f / l1;
    #pragma unroll
    for (int nf = 0; nf < 8; nf++) {
        const int c = nf * 8 + 2 * t4;
        *(uint32_t*)&O[base + (size_t)(q0 + rw) * HID + c] =
            packbf(oacc[nf][0] * inv0, oacc[nf][1] * inv0);
        *(uint32_t*)&O[base + (size_t)(q0 + rw + 8) * HID + c] =
            packbf(oacc[nf][2] * inv1, oacc[nf][3] * inv1);
    }
}

// ---------------- launch -------------------------------------------------------
extern "C" void kernel_launch(void* const* d_in, const int* in_sizes, int n_in,
                              void* d_out, int out_size)
{
    const float* x    = (const float*)d_in[0];
    const float* Wq   = (const float*)d_in[1];
    const float* bq   = (const float*)d_in[2];
    const float* Wk   = (const float*)d_in[3];
    const float* bk   = (const float*)d_in[4];
    const float* Wv   = (const float*)d_in[5];
    const float* bv   = (const float*)d_in[6];
    const float* Wo   = (const float*)d_in[7];
    const float* bo   = (const float*)d_in[8];
    const float* ln_g = (const float*)d_in[9];
    const float* ln_b = (const float*)d_in[10];
    float* out = (float*)d_out;

    __nv_bfloat16 *xn_p, *q_p, *k_p, *v_p, *ctx_p, *wqkv_p, *wo_p;
    cudaGetSymbolAddress((void**)&xn_p,   g_xn);
    cudaGetSymbolAddress((void**)&q_p,    g_q);
    cudaGetSymbolAddress((void**)&k_p,    g_k);
    cudaGetSymbolAddress((void**)&v_p,    g_v);
    cudaGetSymbolAddress((void**)&ctx_p,  g_ctx);
    cudaGetSymbolAddress((void**)&wqkv_p, g_wqkv);
    cudaGetSymbolAddress((void**)&wo_p,   g_wo);

    cudaFuncSetAttribute(attn_mma,
        cudaFuncAttributeMaxDynamicSharedMemorySize, SMEM_ATTN);
    cudaFuncSetAttribute(mma_gemm,
        cudaFuncAttributeMaxDynamicSharedMemorySize, GEMM_SMEM);

    // 0) fused LayerNorm + weight conversion
    dim3 pg(4096, 2);
    prep_kernel<<<pg, 256>>>(x, ln_g, ln_b, xn_p,
                             (const float4*)Wq, (const float4*)Wk,
                             (const float4*)Wv, (const float4*)Wo,
                             (__nv_bfloat162*)wqkv_p, (__nv_bfloat162*)wo_p);

    // 1) fused QKV projection (one GEMM, N=3072)
    dim3 gq(3 * HID / 128, ROWS / 128);
    mma_gemm<<<gq, 256, GEMM_SMEM>>>(xn_p, wqkv_p, bq, bk, bv, nullptr,
                                     q_p, k_p, v_p, nullptr, 0);

    // 2) attention (free-running mbarrier pipeline + corr-skip)
    dim3 ag(SEQ / 128, HEADS, BATCH);
    attn_mma<<<ag, 256, SMEM_ATTN>>>(q_p, k_p, v_p, ctx_p);

    // 3) output projection + bias + residual (fp32 out)
    dim3 go(HID / 128, ROWS / 128);
    mma_gemm<<<go, 256, GEMM_SMEM>>>(ctx_p, wo_p, bo, bo, bo, x,
                                     nullptr, nullptr, nullptr, out, 1);
}